// round 1
// baseline (speedup 1.0000x reference)
#include <cuda_runtime.h>
#include <math.h>

// Problem constants (static per reference)
#define NB    8
#define LQN   900
#define CD    256
#define NHH   8
#define DHH   32
#define DFFN_ 1024
#define LEN_  21760
#define RQ    (NB*LQN)    // 7200
#define RV    (NB*LEN_)   // 174080

// ---------------- scratch (device globals; no allocations allowed) -------------
__device__ float g_qadd[RQ*CD];
__device__ float g_qk  [RQ*512];
__device__ float g_vp  [RQ*CD];
__device__ float g_attn[RQ*CD];
__device__ float g_tmp [RQ*CD];
__device__ float g_tgt1[RQ*CD];
__device__ float g_q2  [RQ*CD];
__device__ float g_off [RQ*CD];
__device__ float g_aw  [RQ*128];
__device__ float g_value[(size_t)RV*CD];
__device__ float g_samp[RQ*CD];
__device__ float g_tgt2[RQ*CD];
__device__ float g_ffn1[RQ*DFFN_];

// ---------------- generic Y[M,N] = X[M,K] @ W[N,K]^T + b, opt relu/mask --------
__global__ __launch_bounds__(256)
void gemm_kernel(const float* __restrict__ X, const float* __restrict__ W,
                 const float* __restrict__ bias, float* __restrict__ Y,
                 int M, int Nn, int K, int relu, const unsigned char* __restrict__ mask)
{
    __shared__ float As[16][65];
    __shared__ float Bs[16][65];
    int bm = blockIdx.y * 64, bn = blockIdx.x * 64;
    int tid = threadIdx.x;
    int lk = tid & 15, lrow = tid >> 4;
    int tx = tid & 15, ty = tid >> 4;
    float acc[4][4] = {};
    for (int k0 = 0; k0 < K; k0 += 16) {
        #pragma unroll
        for (int j = 0; j < 4; j++) {
            int m = lrow + j * 16;
            int gm = bm + m;
            As[lk][m] = (gm < M)  ? X[(size_t)gm * K + k0 + lk] : 0.f;
            int gn = bn + m;
            Bs[lk][m] = (gn < Nn) ? W[(size_t)gn * K + k0 + lk] : 0.f;
        }
        __syncthreads();
        #pragma unroll
        for (int kk = 0; kk < 16; kk++) {
            float a[4], b[4];
            #pragma unroll
            for (int i = 0; i < 4; i++) a[i] = As[kk][ty*4+i];
            #pragma unroll
            for (int j = 0; j < 4; j++) b[j] = Bs[kk][tx*4+j];
            #pragma unroll
            for (int i = 0; i < 4; i++)
                #pragma unroll
                for (int j = 0; j < 4; j++)
                    acc[i][j] += a[i] * b[j];
        }
        __syncthreads();
    }
    #pragma unroll
    for (int i = 0; i < 4; i++) {
        int row = bm + ty*4 + i;
        if (row >= M) continue;
        bool mz = (mask != nullptr) && (mask[row] != 0);
        #pragma unroll
        for (int j = 0; j < 4; j++) {
            int col = bn + tx*4 + j;
            if (col >= Nn) continue;
            float v = acc[i][j] + bias[col];
            if (relu) v = fmaxf(v, 0.f);
            if (mz) v = 0.f;
            Y[(size_t)row * Nn + col] = v;
        }
    }
}

// ---------------- elementwise add ---------------------------------------------
__global__ void add_kernel(const float* __restrict__ a, const float* __restrict__ b,
                           float* __restrict__ y, int n)
{
    int i = blockIdx.x * blockDim.x + threadIdx.x;
    if (i < n) y[i] = a[i] + b[i];
}

// ---------------- Y = LayerNorm(A+B) over C=256, per-row block -----------------
__global__ __launch_bounds__(256)
void add_ln_kernel(const float* __restrict__ A, const float* __restrict__ B,
                   const float* __restrict__ g, const float* __restrict__ bt,
                   float* __restrict__ Y)
{
    int r = blockIdx.x;
    int c = threadIdx.x;
    size_t idx = (size_t)r * 256 + c;
    float x = A[idx] + B[idx];
    __shared__ float s1[8], s2[8];
    float v1 = x, v2 = x * x;
    #pragma unroll
    for (int o = 16; o > 0; o >>= 1) {
        v1 += __shfl_xor_sync(0xFFFFFFFFu, v1, o);
        v2 += __shfl_xor_sync(0xFFFFFFFFu, v2, o);
    }
    int w = c >> 5;
    if ((c & 31) == 0) { s1[w] = v1; s2[w] = v2; }
    __syncthreads();
    float t1 = 0.f, t2 = 0.f;
    #pragma unroll
    for (int i = 0; i < 8; i++) { t1 += s1[i]; t2 += s2[i]; }
    float mean = t1 * (1.f/256.f);
    float var  = t2 * (1.f/256.f) - mean * mean;
    float inv  = rsqrtf(var + 1e-5f);
    Y[idx] = (x - mean) * inv * g[c] + bt[c];
}

// ---------------- softmax over groups of 16 (attention weights) ----------------
__global__ void softmax16_kernel(float* __restrict__ a, int rows)
{
    int r = blockIdx.x * blockDim.x + threadIdx.x;
    if (r >= rows) return;
    float* p = a + (size_t)r * 16;
    float e[16];
    float m = p[0];
    #pragma unroll
    for (int i = 1; i < 16; i++) m = fmaxf(m, p[i]);
    float s = 0.f;
    #pragma unroll
    for (int i = 0; i < 16; i++) { e[i] = expf(p[i] - m); s += e[i]; }
    float inv = 1.f / s;
    #pragma unroll
    for (int i = 0; i < 16; i++) p[i] = e[i] * inv;
}

// ---------------- fused self-attention ----------------------------------------
// grid (7, NH, NB), 256 threads. K tile (900x32) resident in SMEM (transposed),
// scores tile [k][16] in SMEM, softmax in-place, split-key PV with warp reduce.
// smem floats: KsT 32*904=28928 | QsT 512 | sc 904*20=18080 | red 4096 | rowsum 16
#define ATT_SMEM_FLOATS (28928 + 512 + 18080 + 4096 + 16)
#define ATT_SMEM_BYTES  (ATT_SMEM_FLOATS * 4)

__global__ __launch_bounds__(256)
void attn_kernel(const float* __restrict__ qk, const float* __restrict__ vp,
                 float* __restrict__ outp)
{
    extern __shared__ float sm[];
    float* KsT    = sm;                    // [32][904]
    float* QsT    = sm + 28928;            // [32][16]
    float* sc     = QsT + 512;             // [904][20] k-major scores
    float* red    = sc + 18080;            // [8][16][32]
    float* rowsum = red + 4096;            // [16]

    int b = blockIdx.z, h = blockIdx.y;
    int tid = threadIdx.x;
    int w = tid >> 5, lane = tid & 31;
    const float scale = 0.17677669529663687f; // 1/sqrt(32)

    // load K transposed: KsT[d][k]
    const float* Kg = qk + (size_t)(b * 900) * 512 + 256 + h * 32;
    for (int idx = tid; idx < 900 * 32; idx += 256) {
        int k = idx >> 5, d = idx & 31;
        KsT[d * 904 + k] = Kg[(size_t)k * 512 + d];
    }
    int q0   = blockIdx.x * 129;
    int qend = min(900, q0 + 129);
    __syncthreads();

    int txk = tid & 63, tyq = tid >> 6;

    for (int qt = q0; qt < qend; qt += 16) {
        int nq = min(16, qend - qt);
        // load Q tile transposed, prescaled
        for (int idx = tid; idx < 512; idx += 256) {
            int d = idx >> 4, q = idx & 15;
            QsT[d * 16 + q] = (q < nq)
                ? qk[(size_t)(b * 900 + qt + q) * 512 + h * 32 + d] * scale : 0.f;
        }
        __syncthreads();

        // pass 1: scores[k][q] = Q . K  (4q x 4k register tile per thread)
        for (int kt = 0; kt < 4; kt++) {
            int kb = kt * 256 + txk * 4;
            if (kb > 900) continue;  // kb==900 reads pad cols; stores guarded below
            float acc[4][4] = {};
            #pragma unroll
            for (int d = 0; d < 32; d++) {
                float4 a4 = *(const float4*)&QsT[d * 16 + tyq * 4];
                float4 b4 = *(const float4*)&KsT[d * 904 + kb];
                acc[0][0] += a4.x * b4.x; acc[0][1] += a4.x * b4.y;
                acc[0][2] += a4.x * b4.z; acc[0][3] += a4.x * b4.w;
                acc[1][0] += a4.y * b4.x; acc[1][1] += a4.y * b4.y;
                acc[1][2] += a4.y * b4.z; acc[1][3] += a4.y * b4.w;
                acc[2][0] += a4.z * b4.x; acc[2][1] += a4.z * b4.y;
                acc[2][2] += a4.z * b4.z; acc[2][3] += a4.z * b4.w;
                acc[3][0] += a4.w * b4.x; acc[3][1] += a4.w * b4.y;
                acc[3][2] += a4.w * b4.z; acc[3][3] += a4.w * b4.w;
            }
            #pragma unroll
            for (int j = 0; j < 4; j++) {
                int k = kb + j;
                if (k < 900) {
                    #pragma unroll
                    for (int i = 0; i < 4; i++)
                        sc[k * 20 + tyq * 4 + i] = acc[i][j];
                }
            }
        }
        __syncthreads();

        // softmax per query row (warp per row; 2 rows per warp)
        for (int rr = 0; rr < 2; rr++) {
            int q = w + rr * 8;
            if (q < nq) {
                float m = -1e30f;
                for (int k = lane; k < 900; k += 32) m = fmaxf(m, sc[k * 20 + q]);
                #pragma unroll
                for (int o = 16; o > 0; o >>= 1)
                    m = fmaxf(m, __shfl_xor_sync(0xFFFFFFFFu, m, o));
                float s = 0.f;
                for (int k = lane; k < 900; k += 32) {
                    float e = __expf(sc[k * 20 + q] - m);
                    sc[k * 20 + q] = e;
                    s += e;
                }
                #pragma unroll
                for (int o = 16; o > 0; o >>= 1)
                    s += __shfl_xor_sync(0xFFFFFFFFu, s, o);
                if (lane == 0) rowsum[q] = s;
            }
        }
        __syncthreads();

        // pass 2: out[q][d] = sum_k p[k][q] * V[k][d]; keys split across warps
        float acc2[16];
        #pragma unroll
        for (int q = 0; q < 16; q++) acc2[q] = 0.f;
        const float* Vg = vp + (size_t)(b * 900) * 256 + h * 32 + lane;
        for (int k = w; k < 900; k += 8) {
            float v = Vg[(size_t)k * 256];
            float4 p0 = *(const float4*)&sc[k * 20 + 0];
            float4 p1 = *(const float4*)&sc[k * 20 + 4];
            float4 p2 = *(const float4*)&sc[k * 20 + 8];
            float4 p3 = *(const float4*)&sc[k * 20 + 12];
            acc2[0]  += p0.x * v; acc2[1]  += p0.y * v; acc2[2]  += p0.z * v; acc2[3]  += p0.w * v;
            acc2[4]  += p1.x * v; acc2[5]  += p1.y * v; acc2[6]  += p1.z * v; acc2[7]  += p1.w * v;
            acc2[8]  += p2.x * v; acc2[9]  += p2.y * v; acc2[10] += p2.z * v; acc2[11] += p2.w * v;
            acc2[12] += p3.x * v; acc2[13] += p3.y * v; acc2[14] += p3.z * v; acc2[15] += p3.w * v;
        }
        #pragma unroll
        for (int q = 0; q < 16; q++) red[(w * 16 + q) * 32 + lane] = acc2[q];
        __syncthreads();
        for (int o = tid; o < nq * 32; o += 256) {
            int q = o >> 5, d = o & 31;
            float s = 0.f;
            #pragma unroll
            for (int w2 = 0; w2 < 8; w2++) s += red[(w2 * 16 + q) * 32 + d];
            outp[(size_t)(b * 900 + qt + q) * 256 + h * 32 + d] = s / rowsum[q];
        }
        __syncthreads();
    }
}

// ---------------- MS-deformable sampling ---------------------------------------
// grid = RQ blocks (one per (b,q)), 256 threads = 8 warps (warp = head, lane = dim)
__global__ __launch_bounds__(256)
void sample_kernel(const float* __restrict__ value, const float* __restrict__ off,
                   const float* __restrict__ aw, const float* __restrict__ ref,
                   float* __restrict__ outp)
{
    int bq = blockIdx.x;
    int b = bq / 900;
    int h = threadIdx.x >> 5, lane = threadIdx.x & 31;

    const int hs_arr[4] = {128, 64, 32, 16};
    const int ws_arr[4] = {128, 64, 32, 16};
    const int st_arr[4] = {0, 16384, 20480, 21504};

    const float* offp = off + (size_t)bq * 256 + h * 32;
    const float* ap   = aw  + (size_t)bq * 128 + h * 16;
    const float* refp = ref + (size_t)bq * 8;

    float acc = 0.f;
    #pragma unroll
    for (int l = 0; l < 4; l++) {
        int   hs  = hs_arr[l], ws = ws_arr[l];
        float hsf = (float)hs, wsf = (float)ws;
        const float* vbase = value + ((size_t)b * LEN_ + st_arr[l]) * 256 + h * 32 + lane;
        float rx = refp[l * 2], ry = refp[l * 2 + 1];
        #pragma unroll
        for (int p = 0; p < 4; p++) {
            float ox = offp[l * 8 + p * 2];
            float oy = offp[l * 8 + p * 2 + 1];
            // replicate reference op order exactly: (ref + off/norm)*dim - 0.5
            float x = (rx + ox / wsf) * wsf - 0.5f;
            float y = (ry + oy / hsf) * hsf - 0.5f;
            float x0f = floorf(x), y0f = floorf(y);
            int   x0 = (int)x0f, y0 = (int)y0f;
            float wx = x - x0f, wy = y - y0f;
            float a = ap[l * 4 + p];
            float s = 0.f;
            #pragma unroll
            for (int cy = 0; cy < 2; cy++) {
                #pragma unroll
                for (int cx = 0; cx < 2; cx++) {
                    int xi = x0 + cx, yi = y0 + cy;
                    float wgt = (cx ? wx : 1.f - wx) * (cy ? wy : 1.f - wy);
                    if (xi >= 0 && xi < ws && yi >= 0 && yi < hs)
                        s += wgt * vbase[(size_t)(yi * ws + xi) * 256];
                }
            }
            acc += a * s;
        }
    }
    outp[(size_t)bq * 256 + h * 32 + lane] = acc;
}

// ---------------- launch --------------------------------------------------------
extern "C" void kernel_launch(void* const* d_in, const int* in_sizes, int n_in,
                              void* d_out, int out_size)
{
    const float* tgt      = (const float*)d_in[0];
    const float* qpos     = (const float*)d_in[1];
    const float* refp     = (const float*)d_in[2];
    const float* src      = (const float*)d_in[3];
    // d_in[4] (shapes int64), d_in[5] (level_start int64): static, hardcoded
    const unsigned char* mask = (const unsigned char*)d_in[6];
    const float* sa_in_w  = (const float*)d_in[7];
    const float* sa_in_b  = (const float*)d_in[8];
    const float* sa_out_w = (const float*)d_in[9];
    const float* sa_out_b = (const float*)d_in[10];
    const float* ca_off_w = (const float*)d_in[11];
    const float* ca_off_b = (const float*)d_in[12];
    const float* ca_aw_w  = (const float*)d_in[13];
    const float* ca_aw_b  = (const float*)d_in[14];
    const float* ca_val_w = (const float*)d_in[15];
    const float* ca_val_b = (const float*)d_in[16];
    const float* ca_out_w = (const float*)d_in[17];
    const float* ca_out_b = (const float*)d_in[18];
    const float* n1_g = (const float*)d_in[19];
    const float* n1_b = (const float*)d_in[20];
    const float* n2_g = (const float*)d_in[21];
    const float* n2_b = (const float*)d_in[22];
    const float* n3_g = (const float*)d_in[23];
    const float* n3_b = (const float*)d_in[24];
    const float* f1_w = (const float*)d_in[25];
    const float* f1_b = (const float*)d_in[26];
    const float* f2_w = (const float*)d_in[27];
    const float* f2_b = (const float*)d_in[28];
    float* outp = (float*)d_out;

    float *p_qadd, *p_qk, *p_vp, *p_attn, *p_tmp, *p_tgt1, *p_q2;
    float *p_off, *p_aw, *p_value, *p_samp, *p_tgt2, *p_ffn1;
    cudaGetSymbolAddress((void**)&p_qadd,  g_qadd);
    cudaGetSymbolAddress((void**)&p_qk,    g_qk);
    cudaGetSymbolAddress((void**)&p_vp,    g_vp);
    cudaGetSymbolAddress((void**)&p_attn,  g_attn);
    cudaGetSymbolAddress((void**)&p_tmp,   g_tmp);
    cudaGetSymbolAddress((void**)&p_tgt1,  g_tgt1);
    cudaGetSymbolAddress((void**)&p_q2,    g_q2);
    cudaGetSymbolAddress((void**)&p_off,   g_off);
    cudaGetSymbolAddress((void**)&p_aw,    g_aw);
    cudaGetSymbolAddress((void**)&p_value, g_value);
    cudaGetSymbolAddress((void**)&p_samp,  g_samp);
    cudaGetSymbolAddress((void**)&p_tgt2,  g_tgt2);
    cudaGetSymbolAddress((void**)&p_ffn1,  g_ffn1);

    cudaFuncSetAttribute(attn_kernel, cudaFuncAttributeMaxDynamicSharedMemorySize,
                         ATT_SMEM_BYTES);

    const int nQ = RQ * CD;

    // 1) q = tgt + query_pos
    add_kernel<<<(nQ + 255) / 256, 256>>>(tgt, qpos, p_qadd, nQ);
    // 2) QK projection (W rows 0..511)
    dim3 gQK(512 / 64, (RQ + 63) / 64);
    gemm_kernel<<<gQK, 256>>>(p_qadd, sa_in_w, sa_in_b, p_qk, RQ, 512, 256, 0, nullptr);
    // 3) V projection from tgt (W rows 512..767)
    dim3 g256(256 / 64, (RQ + 63) / 64);
    gemm_kernel<<<g256, 256>>>(tgt, sa_in_w + 512 * 256, sa_in_b + 512, p_vp,
                               RQ, 256, 256, 0, nullptr);
    // 4) fused self-attention
    dim3 gatt(7, NHH, NB);
    attn_kernel<<<gatt, 256, ATT_SMEM_BYTES>>>(p_qk, p_vp, p_attn);
    // 5) out projection
    gemm_kernel<<<g256, 256>>>(p_attn, sa_out_w, sa_out_b, p_tmp, RQ, 256, 256, 0, nullptr);
    // 6) tgt1 = LN(tgt + tgt2, n2)
    add_ln_kernel<<<RQ, 256>>>(tgt, p_tmp, n2_g, n2_b, p_tgt1);
    // 7) deformable query = tgt1 + query_pos
    add_kernel<<<(nQ + 255) / 256, 256>>>(p_tgt1, qpos, p_q2, nQ);
    // 8) offsets
    gemm_kernel<<<g256, 256>>>(p_q2, ca_off_w, ca_off_b, p_off, RQ, 256, 256, 0, nullptr);
    // 9) attention weight logits
    dim3 g128(128 / 64, (RQ + 63) / 64);
    gemm_kernel<<<g128, 256>>>(p_q2, ca_aw_w, ca_aw_b, p_aw, RQ, 128, 256, 0, nullptr);
    // 10) softmax over 16 sampling points
    softmax16_kernel<<<(RQ * 8 + 255) / 256, 256>>>(p_aw, RQ * 8);
    // 11) value projection (with padding mask)
    dim3 gval(256 / 64, (RV + 63) / 64);
    gemm_kernel<<<gval, 256>>>(src, ca_val_w, ca_val_b, p_value, RV, 256, 256, 0, mask);
    // 12) bilinear sampling + weighted sum
    sample_kernel<<<RQ, 256>>>(p_value, p_off, p_aw, refp, p_samp);
    // 13) deformable out projection
    gemm_kernel<<<g256, 256>>>(p_samp, ca_out_w, ca_out_b, p_tmp, RQ, 256, 256, 0, nullptr);
    // 14) tgt2 = LN(tgt1 + tmp, n1)
    add_ln_kernel<<<RQ, 256>>>(p_tgt1, p_tmp, n1_g, n1_b, p_tgt2);
    // 15) FFN up + relu
    dim3 gffn(1024 / 64, (RQ + 63) / 64);
    gemm_kernel<<<gffn, 256>>>(p_tgt2, f1_w, f1_b, p_ffn1, RQ, 1024, 256, 1, nullptr);
    // 16) FFN down
    gemm_kernel<<<g256, 256>>>(p_ffn1, f2_w, f2_b, p_tmp, RQ, 256, 1024, 0, nullptr);
    // 17) out = LN(tgt2 + tmp, n3)
    add_ln_kernel<<<RQ, 256>>>(p_tgt2, p_tmp, n3_g, n3_b, outp);
}

// round 3
// speedup vs baseline: 1.8212x; 1.8212x over previous
#include <cuda_runtime.h>
#include <cuda_bf16.h>
#include <math.h>
#include <stdint.h>

// Problem constants (static per reference)
#define NB    8
#define LQN   900
#define CD    256
#define NHH   8
#define DHH   32
#define DFFN_ 1024
#define LEN_  21760
#define RQ    (NB*LQN)    // 7200
#define RV    (NB*LEN_)   // 174080

// ---------------- scratch (device globals; no allocations allowed) -------------
__device__ float g_qadd[RQ*CD];
__device__ float g_qk  [RQ*512];
__device__ float g_vp  [RQ*CD];
__device__ float g_attn[RQ*CD];
__device__ float g_tmp [RQ*CD];
__device__ float g_tgt1[RQ*CD];
__device__ float g_q2  [RQ*CD];
__device__ float g_off [RQ*CD];
__device__ float g_aw  [RQ*128];
__device__ float g_value[(size_t)RV*CD];
__device__ float g_samp[RQ*CD];
__device__ float g_tgt2[RQ*CD];
__device__ float g_ffn1[RQ*DFFN_];

// ================= bf16 split helpers ===========================================
__device__ __forceinline__ void split2(float x, float y, uint32_t& hi, uint32_t& lo)
{
    __nv_bfloat16 hx = __float2bfloat16(x);
    __nv_bfloat16 hy = __float2bfloat16(y);
    __nv_bfloat16 lx = __float2bfloat16(x - __bfloat162float(hx));
    __nv_bfloat16 ly = __float2bfloat16(y - __bfloat162float(hy));
    hi = (uint32_t)(*(unsigned short*)&hx) | ((uint32_t)(*(unsigned short*)&hy) << 16);
    lo = (uint32_t)(*(unsigned short*)&lx) | ((uint32_t)(*(unsigned short*)&ly) << 16);
}

__device__ __forceinline__ void mma_bf16(float* c, const uint32_t* a, const uint32_t* b)
{
    asm volatile(
        "mma.sync.aligned.m16n8k16.row.col.f32.bf16.bf16.f32 "
        "{%0,%1,%2,%3}, {%4,%5,%6,%7}, {%8,%9}, {%0,%1,%2,%3};"
        : "+f"(c[0]), "+f"(c[1]), "+f"(c[2]), "+f"(c[3])
        : "r"(a[0]), "r"(a[1]), "r"(a[2]), "r"(a[3]), "r"(b[0]), "r"(b[1]));
}

// ================= tensor-core GEMM via mma.sync ================================
// Y[M,N] = X[M,K] @ W[N,K]^T + bias. bf16 hi/lo error-compensated (3 passes).
// Block tile 128x128, 256 threads = 8 warps (2m x 4n), warp tile 64x32.
// K staged in 32-chunks; SMEM rows padded to 40 bf16 (20 words) -> conflict-free.
#define GS 20   // words per SMEM row

__global__ __launch_bounds__(256)
void mma_gemm_kernel(const float* __restrict__ X, const float* __restrict__ W,
                     const float* __restrict__ bias, float* __restrict__ Y,
                     int M, int Nn, int K, int relu, const unsigned char* __restrict__ mask)
{
    __shared__ uint32_t sAh[128*GS], sAl[128*GS], sBh[128*GS], sBl[128*GS];

    int tid = threadIdx.x, wid = tid >> 5, lane = tid & 31;
    int bm = blockIdx.y * 128, bn = blockIdx.x * 128;
    int wm = (wid >> 2) * 64;     // warp m offset in tile
    int wn = (wid & 3) * 32;      // warp n offset in tile
    int g = lane >> 2, tig = lane & 3;

    float acc[4][4][4];
    #pragma unroll
    for (int m = 0; m < 4; m++)
        #pragma unroll
        for (int n = 0; n < 4; n++)
            #pragma unroll
            for (int i = 0; i < 4; i++) acc[m][n][i] = 0.f;

    const int nch = K >> 5;
    for (int kc = 0; kc < nch; kc++) {
        int kk = kc * 32;
        // -------- stage: fp32 -> hi/lo bf16 into padded SMEM ------------------
        #pragma unroll
        for (int i = 0; i < 4; i++) {
            int g4  = tid + i * 256;       // 0..1023 float4 id
            int row = g4 >> 3;             // 0..127
            int c4  = (g4 & 7) * 4;        // col in elems (0,4,..,28)
            int wrd = row * GS + (c4 >> 1);
            // A tile
            float4 v = make_float4(0.f, 0.f, 0.f, 0.f);
            int gr = bm + row;
            if (gr < M) v = *(const float4*)(X + (size_t)gr * K + kk + c4);
            uint32_t h0, l0, h1, l1;
            split2(v.x, v.y, h0, l0);
            split2(v.z, v.w, h1, l1);
            sAh[wrd] = h0; sAh[wrd + 1] = h1;
            sAl[wrd] = l0; sAl[wrd + 1] = l1;
            // B tile (Nn is always a multiple of 128)
            v = *(const float4*)(W + (size_t)(bn + row) * K + kk + c4);
            split2(v.x, v.y, h0, l0);
            split2(v.z, v.w, h1, l1);
            sBh[wrd] = h0; sBh[wrd + 1] = h1;
            sBl[wrd] = l0; sBl[wrd + 1] = l1;
        }
        __syncthreads();

        // -------- compute: 2 k-atoms of 16 ------------------------------------
        #pragma unroll
        for (int ka = 0; ka < 2; ka++) {
            int kw = ka * 8 + tig;         // word col of (k0 + 2*tig)
            uint32_t ah[4][4], al[4][4];
            #pragma unroll
            for (int m = 0; m < 4; m++) {
                int r = wm + m * 16 + g;
                ah[m][0] = sAh[r * GS + kw];
                ah[m][1] = sAh[(r + 8) * GS + kw];
                ah[m][2] = sAh[r * GS + kw + 4];
                ah[m][3] = sAh[(r + 8) * GS + kw + 4];
                al[m][0] = sAl[r * GS + kw];
                al[m][1] = sAl[(r + 8) * GS + kw];
                al[m][2] = sAl[r * GS + kw + 4];
                al[m][3] = sAl[(r + 8) * GS + kw + 4];
            }
            uint32_t bh[4][2], bl[4][2];
            #pragma unroll
            for (int n = 0; n < 4; n++) {
                int rn = wn + n * 8 + g;
                bh[n][0] = sBh[rn * GS + kw];
                bh[n][1] = sBh[rn * GS + kw + 4];
                bl[n][0] = sBl[rn * GS + kw];
                bl[n][1] = sBl[rn * GS + kw + 4];
            }
            #pragma unroll
            for (int m = 0; m < 4; m++)
                #pragma unroll
                for (int n = 0; n < 4; n++) {
                    mma_bf16(acc[m][n], ah[m], bh[n]);
                    mma_bf16(acc[m][n], ah[m], bl[n]);
                    mma_bf16(acc[m][n], al[m], bh[n]);
                }
        }
        __syncthreads();
    }

    // -------- epilogue ---------------------------------------------------------
    #pragma unroll
    for (int m = 0; m < 4; m++) {
        int r0 = bm + wm + m * 16 + g;
        #pragma unroll
        for (int n = 0; n < 4; n++) {
            int c0 = bn + wn + n * 8 + 2 * tig;
            float b0 = bias[c0], b1 = bias[c0 + 1];
            if (r0 < M) {
                float v0 = acc[m][n][0] + b0;
                float v1 = acc[m][n][1] + b1;
                if (relu) { v0 = fmaxf(v0, 0.f); v1 = fmaxf(v1, 0.f); }
                if (mask && mask[r0]) { v0 = 0.f; v1 = 0.f; }
                *(float2*)(Y + (size_t)r0 * Nn + c0) = make_float2(v0, v1);
            }
            if (r0 + 8 < M) {
                float v2 = acc[m][n][2] + b0;
                float v3 = acc[m][n][3] + b1;
                if (relu) { v2 = fmaxf(v2, 0.f); v3 = fmaxf(v3, 0.f); }
                if (mask && mask[r0 + 8]) { v2 = 0.f; v3 = 0.f; }
                *(float2*)(Y + (size_t)(r0 + 8) * Nn + c0) = make_float2(v2, v3);
            }
        }
    }
}

// ---------------- elementwise add ---------------------------------------------
__global__ void add_kernel(const float* __restrict__ a, const float* __restrict__ b,
                           float* __restrict__ y, int n)
{
    int i = blockIdx.x * blockDim.x + threadIdx.x;
    if (i < n) y[i] = a[i] + b[i];
}

// ---------------- Y = LayerNorm(A+B) over C=256, per-row block -----------------
__global__ __launch_bounds__(256)
void add_ln_kernel(const float* __restrict__ A, const float* __restrict__ B,
                   const float* __restrict__ g, const float* __restrict__ bt,
                   float* __restrict__ Y)
{
    int r = blockIdx.x;
    int c = threadIdx.x;
    size_t idx = (size_t)r * 256 + c;
    float x = A[idx] + B[idx];
    __shared__ float s1[8], s2[8];
    float v1 = x, v2 = x * x;
    #pragma unroll
    for (int o = 16; o > 0; o >>= 1) {
        v1 += __shfl_xor_sync(0xFFFFFFFFu, v1, o);
        v2 += __shfl_xor_sync(0xFFFFFFFFu, v2, o);
    }
    int w = c >> 5;
    if ((c & 31) == 0) { s1[w] = v1; s2[w] = v2; }
    __syncthreads();
    float t1 = 0.f, t2 = 0.f;
    #pragma unroll
    for (int i = 0; i < 8; i++) { t1 += s1[i]; t2 += s2[i]; }
    float mean = t1 * (1.f/256.f);
    float var  = t2 * (1.f/256.f) - mean * mean;
    float inv  = rsqrtf(var + 1e-5f);
    Y[idx] = (x - mean) * inv * g[c] + bt[c];
}

// ---------------- softmax over groups of 16 (attention weights) ----------------
__global__ void softmax16_kernel(float* __restrict__ a, int rows)
{
    int r = blockIdx.x * blockDim.x + threadIdx.x;
    if (r >= rows) return;
    float* p = a + (size_t)r * 16;
    float e[16];
    float m = p[0];
    #pragma unroll
    for (int i = 1; i < 16; i++) m = fmaxf(m, p[i]);
    float s = 0.f;
    #pragma unroll
    for (int i = 0; i < 16; i++) { e[i] = expf(p[i] - m); s += e[i]; }
    float inv = 1.f / s;
    #pragma unroll
    for (int i = 0; i < 16; i++) p[i] = e[i] * inv;
}

// ---------------- flash self-attention -----------------------------------------
// grid (15, NH, NB), 256 threads. 64-query x 64-key tiles, online softmax.
__global__ __launch_bounds__(256)
void fattn_kernel(const float* __restrict__ qk, const float* __restrict__ vp,
                  float* __restrict__ outp)
{
    __shared__ float QT[32 * 68];     // [d][q]
    __shared__ float KT[32 * 68];     // [d][k]
    __shared__ float S [64 * 68];     // [q][k]
    __shared__ float Vs[64 * 36];     // [k][d]
    __shared__ float m_s[64], l_s[64], corr[64];

    int b = blockIdx.z, h = blockIdx.y, qb = blockIdx.x;
    int tid = threadIdx.x;
    int w = tid >> 5, lane = tid & 31;
    const float scale = 0.17677669529663687f;   // 1/sqrt(32)

    // load Q tile transposed (prescaled)
    int q0 = qb * 64;
    for (int i = tid; i < 64 * 32; i += 256) {
        int qq = i >> 5, d = i & 31;
        int qg = q0 + qq;
        QT[d * 68 + qq] = (qg < 900)
            ? qk[(size_t)(b * 900 + qg) * 512 + h * 32 + d] * scale : 0.f;
    }
    if (tid < 64) { m_s[tid] = -1e30f; l_s[tid] = 0.f; }

    int q_own = tid >> 2;
    int dg = (tid & 3) * 8;
    float acc[8];
    #pragma unroll
    for (int j = 0; j < 8; j++) acc[j] = 0.f;

    int ty = tid >> 4, tx = tid & 15;

    for (int kt = 0; kt < 15; kt++) {
        int k0 = kt * 64;
        int nk = min(64, 900 - k0);
        __syncthreads();
        // load K tile transposed + V tile
        for (int i = tid; i < 64 * 32; i += 256) {
            int kk = i >> 5, d = i & 31;
            KT[d * 68 + kk] = (kk < nk)
                ? qk[(size_t)(b * 900 + k0 + kk) * 512 + 256 + h * 32 + d] : 0.f;
            Vs[kk * 36 + d] = (kk < nk)
                ? vp[(size_t)(b * 900 + k0 + kk) * 256 + h * 32 + d] : 0.f;
        }
        __syncthreads();

        // S = Q . K^T : 4q x 4k register tile per thread
        {
            float a4[4][4] = {};
            #pragma unroll
            for (int d = 0; d < 32; d++) {
                float4 qv = *(const float4*)&QT[d * 68 + ty * 4];
                float4 kv = *(const float4*)&KT[d * 68 + tx * 4];
                a4[0][0] += qv.x * kv.x; a4[0][1] += qv.x * kv.y; a4[0][2] += qv.x * kv.z; a4[0][3] += qv.x * kv.w;
                a4[1][0] += qv.y * kv.x; a4[1][1] += qv.y * kv.y; a4[1][2] += qv.y * kv.z; a4[1][3] += qv.y * kv.w;
                a4[2][0] += qv.z * kv.x; a4[2][1] += qv.z * kv.y; a4[2][2] += qv.z * kv.z; a4[2][3] += qv.z * kv.w;
                a4[3][0] += qv.w * kv.x; a4[3][1] += qv.w * kv.y; a4[3][2] += qv.w * kv.z; a4[3][3] += qv.w * kv.w;
            }
            #pragma unroll
            for (int i = 0; i < 4; i++)
                *(float4*)&S[(ty * 4 + i) * 68 + tx * 4] = make_float4(a4[i][0], a4[i][1], a4[i][2], a4[i][3]);
        }
        __syncthreads();

        // online softmax: warp w handles rows w*8 .. w*8+7
        #pragma unroll
        for (int r = 0; r < 8; r++) {
            int q = w * 8 + r;
            float* srow = &S[q * 68];
            float v0 = (lane      < nk) ? srow[lane]      : -1e30f;
            float v1 = (lane + 32 < nk) ? srow[lane + 32] : -1e30f;
            float mt = fmaxf(v0, v1);
            #pragma unroll
            for (int o = 16; o > 0; o >>= 1)
                mt = fmaxf(mt, __shfl_xor_sync(0xFFFFFFFFu, mt, o));
            float m_old = m_s[q];
            float m_new = fmaxf(m_old, mt);
            float p0 = (lane      < nk) ? __expf(v0 - m_new) : 0.f;
            float p1 = (lane + 32 < nk) ? __expf(v1 - m_new) : 0.f;
            srow[lane]      = p0;
            srow[lane + 32] = p1;
            float ps = p0 + p1;
            #pragma unroll
            for (int o = 16; o > 0; o >>= 1)
                ps += __shfl_xor_sync(0xFFFFFFFFu, ps, o);
            if (lane == 0) {
                float c = __expf(m_old - m_new);
                corr[q] = c;
                l_s[q]  = l_s[q] * c + ps;
                m_s[q]  = m_new;
            }
        }
        __syncthreads();

        // rescale + PV
        {
            float c = corr[q_own];
            #pragma unroll
            for (int j = 0; j < 8; j++) acc[j] *= c;
            const float* srow = &S[q_own * 68];
            #pragma unroll 4
            for (int k = 0; k < 64; k++) {
                float p = srow[k];
                float4 v0 = *(const float4*)&Vs[k * 36 + dg];
                float4 v1 = *(const float4*)&Vs[k * 36 + dg + 4];
                acc[0] += p * v0.x; acc[1] += p * v0.y; acc[2] += p * v0.z; acc[3] += p * v0.w;
                acc[4] += p * v1.x; acc[5] += p * v1.y; acc[6] += p * v1.z; acc[7] += p * v1.w;
            }
        }
    }
    __syncthreads();
    int qg = q0 + q_own;
    if (qg < 900) {
        float inv = 1.f / l_s[q_own];
        float* o = outp + (size_t)(b * 900 + qg) * 256 + h * 32 + dg;
        *(float4*)o       = make_float4(acc[0]*inv, acc[1]*inv, acc[2]*inv, acc[3]*inv);
        *(float4*)(o + 4) = make_float4(acc[4]*inv, acc[5]*inv, acc[6]*inv, acc[7]*inv);
    }
}

// ---------------- MS-deformable sampling ---------------------------------------
__global__ __launch_bounds__(256)
void sample_kernel(const float* __restrict__ value, const float* __restrict__ off,
                   const float* __restrict__ aw, const float* __restrict__ ref,
                   float* __restrict__ outp)
{
    int bq = blockIdx.x;
    int b = bq / 900;
    int h = threadIdx.x >> 5, lane = threadIdx.x & 31;

    const int hs_arr[4] = {128, 64, 32, 16};
    const int ws_arr[4] = {128, 64, 32, 16};
    const int st_arr[4] = {0, 16384, 20480, 21504};

    const float* offp = off + (size_t)bq * 256 + h * 32;
    const float* ap   = aw  + (size_t)bq * 128 + h * 16;
    const float* refp = ref + (size_t)bq * 8;

    float acc = 0.f;
    #pragma unroll
    for (int l = 0; l < 4; l++) {
        int   hs  = hs_arr[l], ws = ws_arr[l];
        float hsf = (float)hs, wsf = (float)ws;
        const float* vbase = value + ((size_t)b * LEN_ + st_arr[l]) * 256 + h * 32 + lane;
        float rx = refp[l * 2], ry = refp[l * 2 + 1];
        #pragma unroll
        for (int p = 0; p < 4; p++) {
            float ox = offp[l * 8 + p * 2];
            float oy = offp[l * 8 + p * 2 + 1];
            float x = (rx + ox / wsf) * wsf - 0.5f;
            float y = (ry + oy / hsf) * hsf - 0.5f;
            float x0f = floorf(x), y0f = floorf(y);
            int   x0 = (int)x0f, y0 = (int)y0f;
            float wx = x - x0f, wy = y - y0f;
            float a = ap[l * 4 + p];
            float s = 0.f;
            #pragma unroll
            for (int cy = 0; cy < 2; cy++) {
                #pragma unroll
                for (int cx = 0; cx < 2; cx++) {
                    int xi = x0 + cx, yi = y0 + cy;
                    float wgt = (cx ? wx : 1.f - wx) * (cy ? wy : 1.f - wy);
                    if (xi >= 0 && xi < ws && yi >= 0 && yi < hs)
                        s += wgt * vbase[(size_t)(yi * ws + xi) * 256];
                }
            }
            acc += a * s;
        }
    }
    outp[(size_t)bq * 256 + h * 32 + lane] = acc;
}

// ---------------- launch --------------------------------------------------------
static inline void tgemm(const float* X, const float* W, const float* b, float* Y,
                         int M, int Nn, int K, int relu, const unsigned char* mask)
{
    dim3 g(Nn / 128, (M + 127) / 128);
    mma_gemm_kernel<<<g, 256>>>(X, W, b, Y, M, Nn, K, relu, mask);
}

extern "C" void kernel_launch(void* const* d_in, const int* in_sizes, int n_in,
                              void* d_out, int out_size)
{
    const float* tgt      = (const float*)d_in[0];
    const float* qpos     = (const float*)d_in[1];
    const float* refp     = (const float*)d_in[2];
    const float* src      = (const float*)d_in[3];
    const unsigned char* mask = (const unsigned char*)d_in[6];
    const float* sa_in_w  = (const float*)d_in[7];
    const float* sa_in_b  = (const float*)d_in[8];
    const float* sa_out_w = (const float*)d_in[9];
    const float* sa_out_b = (const float*)d_in[10];
    const float* ca_off_w = (const float*)d_in[11];
    const float* ca_off_b = (const float*)d_in[12];
    const float* ca_aw_w  = (const float*)d_in[13];
    const float* ca_aw_b  = (const float*)d_in[14];
    const float* ca_val_w = (const float*)d_in[15];
    const float* ca_val_b = (const float*)d_in[16];
    const float* ca_out_w = (const float*)d_in[17];
    const float* ca_out_b = (const float*)d_in[18];
    const float* n1_g = (const float*)d_in[19];
    const float* n1_b = (const float*)d_in[20];
    const float* n2_g = (const float*)d_in[21];
    const float* n2_b = (const float*)d_in[22];
    const float* n3_g = (const float*)d_in[23];
    const float* n3_b = (const float*)d_in[24];
    const float* f1_w = (const float*)d_in[25];
    const float* f1_b = (const float*)d_in[26];
    const float* f2_w = (const float*)d_in[27];
    const float* f2_b = (const float*)d_in[28];
    float* outp = (float*)d_out;

    float *p_qadd, *p_qk, *p_vp, *p_attn, *p_tmp, *p_tgt1, *p_q2;
    float *p_off, *p_aw, *p_value, *p_samp, *p_tgt2, *p_ffn1;
    cudaGetSymbolAddress((void**)&p_qadd,  g_qadd);
    cudaGetSymbolAddress((void**)&p_qk,    g_qk);
    cudaGetSymbolAddress((void**)&p_vp,    g_vp);
    cudaGetSymbolAddress((void**)&p_attn,  g_attn);
    cudaGetSymbolAddress((void**)&p_tmp,   g_tmp);
    cudaGetSymbolAddress((void**)&p_tgt1,  g_tgt1);
    cudaGetSymbolAddress((void**)&p_q2,    g_q2);
    cudaGetSymbolAddress((void**)&p_off,   g_off);
    cudaGetSymbolAddress((void**)&p_aw,    g_aw);
    cudaGetSymbolAddress((void**)&p_value, g_value);
    cudaGetSymbolAddress((void**)&p_samp,  g_samp);
    cudaGetSymbolAddress((void**)&p_tgt2,  g_tgt2);
    cudaGetSymbolAddress((void**)&p_ffn1,  g_ffn1);

    const int nQ = RQ * CD;

    // 1) q = tgt + query_pos
    add_kernel<<<(nQ + 255) / 256, 256>>>(tgt, qpos, p_qadd, nQ);
    // 2) QK projection
    tgemm(p_qadd, sa_in_w, sa_in_b, p_qk, RQ, 512, 256, 0, nullptr);
    // 3) V projection
    tgemm(tgt, sa_in_w + 512 * 256, sa_in_b + 512, p_vp, RQ, 256, 256, 0, nullptr);
    // 4) flash self-attention
    dim3 gatt(15, NHH, NB);
    fattn_kernel<<<gatt, 256>>>(p_qk, p_vp, p_attn);
    // 5) out projection
    tgemm(p_attn, sa_out_w, sa_out_b, p_tmp, RQ, 256, 256, 0, nullptr);
    // 6) tgt1 = LN(tgt + tgt2, n2)
    add_ln_kernel<<<RQ, 256>>>(tgt, p_tmp, n2_g, n2_b, p_tgt1);
    // 7) deformable query
    add_kernel<<<(nQ + 255) / 256, 256>>>(p_tgt1, qpos, p_q2, nQ);
    // 8) offsets
    tgemm(p_q2, ca_off_w, ca_off_b, p_off, RQ, 256, 256, 0, nullptr);
    // 9) attention-weight logits
    tgemm(p_q2, ca_aw_w, ca_aw_b, p_aw, RQ, 128, 256, 0, nullptr);
    // 10) softmax over 16 sampling points
    softmax16_kernel<<<(RQ * 8 + 255) / 256, 256>>>(p_aw, RQ * 8);
    // 11) value projection (with padding mask)
    tgemm(src, ca_val_w, ca_val_b, p_value, RV, 256, 256, 0, mask);
    // 12) bilinear sampling + weighted sum
    sample_kernel<<<RQ, 256>>>(p_value, p_off, p_aw, refp, p_samp);
    // 13) deformable out projection
    tgemm(p_samp, ca_out_w, ca_out_b, p_tmp, RQ, 256, 256, 0, nullptr);
    // 14) tgt2 = LN(tgt1 + tmp, n1)
    add_ln_kernel<<<RQ, 256>>>(p_tgt1, p_tmp, n1_g, n1_b, p_tgt2);
    // 15) FFN up + relu
    tgemm(p_tgt2, f1_w, f1_b, p_ffn1, RQ, 1024, 256, 1, nullptr);
    // 16) FFN down
    tgemm(p_ffn1, f2_w, f2_b, p_tmp, RQ, 256, 1024, 0, nullptr);
    // 17) out = LN(tgt2 + tmp, n3)
    add_ln_kernel<<<RQ, 256>>>(p_tgt2, p_tmp, n3_g, n3_b, outp);
}

// round 4
// speedup vs baseline: 2.3037x; 1.2649x over previous
#include <cuda_runtime.h>
#include <cuda_bf16.h>
#include <math.h>
#include <stdint.h>

// Problem constants (static per reference)
#define NB    8
#define LQN   900
#define CD    256
#define NHH   8
#define DHH   32
#define DFFN_ 1024
#define LEN_  21760
#define RQ    (NB*LQN)    // 7200
#define RV    (NB*LEN_)   // 174080

// ---------------- scratch (device globals; no allocations allowed) -------------
__device__ float g_qadd[RQ*CD];
__device__ float g_qk  [RQ*512];
__device__ float g_vp  [RQ*CD];
__device__ float g_attn[RQ*CD];
__device__ float g_tmp [RQ*CD];
__device__ float g_tgt1[RQ*CD];
__device__ float g_q2  [RQ*CD];
__device__ float g_off [RQ*CD];
__device__ float g_aw  [RQ*128];
__device__ float g_value[(size_t)RV*CD];
__device__ float g_samp[RQ*CD];
__device__ float g_tgt2[RQ*CD];
__device__ float g_ffn1[RQ*DFFN_];
// pre-split weights (bf16x2 words): 507904 words each
__device__ uint32_t g_wh[507904];
__device__ uint32_t g_wl[507904];

// ================= bf16 split helpers ===========================================
__device__ __forceinline__ void split2(float x, float y, uint32_t& hi, uint32_t& lo)
{
    __nv_bfloat16 hx = __float2bfloat16(x);
    __nv_bfloat16 hy = __float2bfloat16(y);
    __nv_bfloat16 lx = __float2bfloat16(x - __bfloat162float(hx));
    __nv_bfloat16 ly = __float2bfloat16(y - __bfloat162float(hy));
    hi = (uint32_t)(*(unsigned short*)&hx) | ((uint32_t)(*(unsigned short*)&hy) << 16);
    lo = (uint32_t)(*(unsigned short*)&lx) | ((uint32_t)(*(unsigned short*)&ly) << 16);
}

__device__ __forceinline__ void mma_bf16(float* c, const uint32_t* a, const uint32_t* b)
{
    asm volatile(
        "mma.sync.aligned.m16n8k16.row.col.f32.bf16.bf16.f32 "
        "{%0,%1,%2,%3}, {%4,%5,%6,%7}, {%8,%9}, {%0,%1,%2,%3};"
        : "+f"(c[0]), "+f"(c[1]), "+f"(c[2]), "+f"(c[3])
        : "r"(a[0]), "r"(a[1]), "r"(a[2]), "r"(a[3]), "r"(b[0]), "r"(b[1]));
}

// ---------------- weight pre-split ----------------------------------------------
__global__ void split_w_kernel(const float* __restrict__ W, uint32_t* __restrict__ Wh,
                               uint32_t* __restrict__ Wl, int nw)
{
    int i = blockIdx.x * 256 + threadIdx.x;
    if (i < nw) {
        float2 v = *(const float2*)(W + 2 * (size_t)i);
        uint32_t h, l; split2(v.x, v.y, h, l);
        Wh[i] = h; Wl[i] = l;
    }
}

// ================= tensor-core GEMM via mma.sync (pre-split B) ===================
// Y[M,N] = X[M,K] @ W[N,K]^T + bias. bf16 hi/lo error-compensated (3 passes).
// Block tile 128x128, 256 threads = 8 warps (2m x 4n), warp tile 64x32.
#define GS 20   // words per SMEM row

__global__ __launch_bounds__(256)
void mma_gemm_kernel(const float* __restrict__ X, const uint32_t* __restrict__ Wh,
                     const uint32_t* __restrict__ Wl,
                     const float* __restrict__ bias, float* __restrict__ Y,
                     int M, int Nn, int K, int relu, const unsigned char* __restrict__ mask)
{
    __shared__ uint32_t sAh[128*GS], sAl[128*GS], sBh[128*GS], sBl[128*GS];

    int tid = threadIdx.x, wid = tid >> 5, lane = tid & 31;
    int bm = blockIdx.y * 128, bn = blockIdx.x * 128;
    int wm = (wid >> 2) * 64;     // warp m offset in tile
    int wn = (wid & 3) * 32;      // warp n offset in tile
    int g = lane >> 2, tig = lane & 3;

    float acc[4][4][4];
    #pragma unroll
    for (int m = 0; m < 4; m++)
        #pragma unroll
        for (int n = 0; n < 4; n++)
            #pragma unroll
            for (int i = 0; i < 4; i++) acc[m][n][i] = 0.f;

    const int nch = K >> 5;
    for (int kc = 0; kc < nch; kc++) {
        int kk = kc * 32;
        #pragma unroll
        for (int i = 0; i < 4; i++) {
            int g4  = tid + i * 256;       // 0..1023 quad id
            int row = g4 >> 3;             // 0..127
            int c4  = (g4 & 7) * 4;        // col in elems
            int wrd = row * GS + (c4 >> 1);
            // A tile: fp32 -> hi/lo split
            float4 v = make_float4(0.f, 0.f, 0.f, 0.f);
            int gr = bm + row;
            if (gr < M) v = *(const float4*)(X + (size_t)gr * K + kk + c4);
            uint32_t h0, l0, h1, l1;
            split2(v.x, v.y, h0, l0);
            split2(v.z, v.w, h1, l1);
            sAh[wrd] = h0; sAh[wrd + 1] = h1;
            sAl[wrd] = l0; sAl[wrd + 1] = l1;
            // B tile: direct copy of pre-split words
            size_t wo = ((size_t)(bn + row) * K + kk + c4) >> 1;
            uint2 wh = *(const uint2*)(Wh + wo);
            uint2 wl = *(const uint2*)(Wl + wo);
            sBh[wrd] = wh.x; sBh[wrd + 1] = wh.y;
            sBl[wrd] = wl.x; sBl[wrd + 1] = wl.y;
        }
        __syncthreads();

        #pragma unroll
        for (int ka = 0; ka < 2; ka++) {
            int kw = ka * 8 + tig;
            uint32_t ah[4][4], al[4][4];
            #pragma unroll
            for (int m = 0; m < 4; m++) {
                int r = wm + m * 16 + g;
                ah[m][0] = sAh[r * GS + kw];
                ah[m][1] = sAh[(r + 8) * GS + kw];
                ah[m][2] = sAh[r * GS + kw + 4];
                ah[m][3] = sAh[(r + 8) * GS + kw + 4];
                al[m][0] = sAl[r * GS + kw];
                al[m][1] = sAl[(r + 8) * GS + kw];
                al[m][2] = sAl[r * GS + kw + 4];
                al[m][3] = sAl[(r + 8) * GS + kw + 4];
            }
            uint32_t bh[4][2], bl[4][2];
            #pragma unroll
            for (int n = 0; n < 4; n++) {
                int rn = wn + n * 8 + g;
                bh[n][0] = sBh[rn * GS + kw];
                bh[n][1] = sBh[rn * GS + kw + 4];
                bl[n][0] = sBl[rn * GS + kw];
                bl[n][1] = sBl[rn * GS + kw + 4];
            }
            #pragma unroll
            for (int m = 0; m < 4; m++)
                #pragma unroll
                for (int n = 0; n < 4; n++) {
                    mma_bf16(acc[m][n], ah[m], bh[n]);
                    mma_bf16(acc[m][n], ah[m], bl[n]);
                    mma_bf16(acc[m][n], al[m], bh[n]);
                }
        }
        __syncthreads();
    }

    #pragma unroll
    for (int m = 0; m < 4; m++) {
        int r0 = bm + wm + m * 16 + g;
        #pragma unroll
        for (int n = 0; n < 4; n++) {
            int c0 = bn + wn + n * 8 + 2 * tig;
            float b0 = bias[c0], b1 = bias[c0 + 1];
            if (r0 < M) {
                float v0 = acc[m][n][0] + b0;
                float v1 = acc[m][n][1] + b1;
                if (relu) { v0 = fmaxf(v0, 0.f); v1 = fmaxf(v1, 0.f); }
                if (mask && mask[r0]) { v0 = 0.f; v1 = 0.f; }
                *(float2*)(Y + (size_t)r0 * Nn + c0) = make_float2(v0, v1);
            }
            if (r0 + 8 < M) {
                float v2 = acc[m][n][2] + b0;
                float v3 = acc[m][n][3] + b1;
                if (relu) { v2 = fmaxf(v2, 0.f); v3 = fmaxf(v3, 0.f); }
                if (mask && mask[r0 + 8]) { v2 = 0.f; v3 = 0.f; }
                *(float2*)(Y + (size_t)(r0 + 8) * Nn + c0) = make_float2(v2, v3);
            }
        }
    }
}

// ---------------- elementwise add ---------------------------------------------
__global__ void add_kernel(const float* __restrict__ a, const float* __restrict__ b,
                           float* __restrict__ y, int n)
{
    int i = blockIdx.x * blockDim.x + threadIdx.x;
    if (i < n) y[i] = a[i] + b[i];
}

// ---------------- Y = LayerNorm(A+B) over C=256, per-row block -----------------
__global__ __launch_bounds__(256)
void add_ln_kernel(const float* __restrict__ A, const float* __restrict__ B,
                   const float* __restrict__ g, const float* __restrict__ bt,
                   float* __restrict__ Y)
{
    int r = blockIdx.x;
    int c = threadIdx.x;
    size_t idx = (size_t)r * 256 + c;
    float x = A[idx] + B[idx];
    __shared__ float s1[8], s2[8];
    float v1 = x, v2 = x * x;
    #pragma unroll
    for (int o = 16; o > 0; o >>= 1) {
        v1 += __shfl_xor_sync(0xFFFFFFFFu, v1, o);
        v2 += __shfl_xor_sync(0xFFFFFFFFu, v2, o);
    }
    int w = c >> 5;
    if ((c & 31) == 0) { s1[w] = v1; s2[w] = v2; }
    __syncthreads();
    float t1 = 0.f, t2 = 0.f;
    #pragma unroll
    for (int i = 0; i < 8; i++) { t1 += s1[i]; t2 += s2[i]; }
    float mean = t1 * (1.f/256.f);
    float var  = t2 * (1.f/256.f) - mean * mean;
    float inv  = rsqrtf(var + 1e-5f);
    Y[idx] = (x - mean) * inv * g[c] + bt[c];
}

// ---------------- softmax over groups of 16 (attention weights) ----------------
__global__ void softmax16_kernel(float* __restrict__ a, int rows)
{
    int r = blockIdx.x * blockDim.x + threadIdx.x;
    if (r >= rows) return;
    float* p = a + (size_t)r * 16;
    float e[16];
    float m = p[0];
    #pragma unroll
    for (int i = 1; i < 16; i++) m = fmaxf(m, p[i]);
    float s = 0.f;
    #pragma unroll
    for (int i = 0; i < 16; i++) { e[i] = expf(p[i] - m); s += e[i]; }
    float inv = 1.f / s;
    #pragma unroll
    for (int i = 0; i < 16; i++) p[i] = e[i] * inv;
}

// ---------------- tensor-core flash self-attention ------------------------------
// grid (15, NH, NB), 128 threads = 4 warps, 16 queries/warp, 64-key tiles.
// QK^T and PV via mma.m16n8k16 with bf16 hi/lo compensation; softmax in registers.
__global__ __launch_bounds__(128)
void fattn_mma_kernel(const float* __restrict__ qk, const float* __restrict__ vp,
                      float* __restrict__ outp)
{
    __shared__ uint32_t Qh[64*20], Ql[64*20];
    __shared__ uint32_t Kh[64*20], Kl[64*20];
    __shared__ uint32_t Vh[32*36], Vl[32*36];

    int b = blockIdx.z, h = blockIdx.y, qb = blockIdx.x;
    int tid = threadIdx.x, w = tid >> 5, lane = tid & 31;
    int g = lane >> 2, tig = lane & 3;
    int q0 = qb * 64;
    const float scale = 0.17677669529663687f;   // 1/sqrt(32)

    // stage Q (prescaled) hi/lo
    for (int idx = tid; idx < 64 * 16; idx += 128) {
        int row = idx >> 4, wc = idx & 15;
        int qg = q0 + row;
        float2 v = make_float2(0.f, 0.f);
        if (qg < 900) v = *(const float2*)(qk + (size_t)(b * 900 + qg) * 512 + h * 32 + 2 * wc);
        uint32_t hi, lo; split2(v.x * scale, v.y * scale, hi, lo);
        Qh[row * 20 + wc] = hi; Ql[row * 20 + wc] = lo;
    }
    __syncthreads();

    // Q fragments persist in registers across all key tiles
    uint32_t qh[2][4], ql[2][4];
    int wq = w * 16;
    #pragma unroll
    for (int ka = 0; ka < 2; ka++) {
        int base = 8 * ka + tig;
        qh[ka][0] = Qh[(wq + g) * 20 + base];     qh[ka][1] = Qh[(wq + g + 8) * 20 + base];
        qh[ka][2] = Qh[(wq + g) * 20 + base + 4]; qh[ka][3] = Qh[(wq + g + 8) * 20 + base + 4];
        ql[ka][0] = Ql[(wq + g) * 20 + base];     ql[ka][1] = Ql[(wq + g + 8) * 20 + base];
        ql[ka][2] = Ql[(wq + g) * 20 + base + 4]; ql[ka][3] = Ql[(wq + g + 8) * 20 + base + 4];
    }

    float out[4][4];
    #pragma unroll
    for (int n = 0; n < 4; n++) { out[n][0]=0.f; out[n][1]=0.f; out[n][2]=0.f; out[n][3]=0.f; }
    float m0 = -1e30f, m1 = -1e30f, l0 = 0.f, l1 = 0.f;

    for (int kt = 0; kt < 15; kt++) {
        int k0 = kt * 64;
        __syncthreads();
        // stage K tile hi/lo
        for (int idx = tid; idx < 64 * 16; idx += 128) {
            int row = idx >> 4, wc = idx & 15;
            int kg = k0 + row;
            float2 v = make_float2(0.f, 0.f);
            if (kg < 900)
                v = *(const float2*)(qk + (size_t)(b * 900 + kg) * 512 + 256 + h * 32 + 2 * wc);
            uint32_t hi, lo; split2(v.x, v.y, hi, lo);
            Kh[row * 20 + wc] = hi; Kl[row * 20 + wc] = lo;
        }
        // stage V transposed hi/lo: Vh[d][key-pair]
        for (int idx = tid; idx < 32 * 32; idx += 128) {
            int d = idx >> 5, wc = idx & 31;
            int kg = k0 + 2 * wc;
            float v0 = (kg     < 900) ? vp[(size_t)(b * 900 + kg    ) * 256 + h * 32 + d] : 0.f;
            float v1 = (kg + 1 < 900) ? vp[(size_t)(b * 900 + kg + 1) * 256 + h * 32 + d] : 0.f;
            uint32_t hi, lo; split2(v0, v1, hi, lo);
            Vh[d * 36 + wc] = hi; Vl[d * 36 + wc] = lo;
        }
        __syncthreads();

        // ---- S = Q.K^T ----
        float s[8][4];
        #pragma unroll
        for (int j = 0; j < 8; j++) { s[j][0]=0.f; s[j][1]=0.f; s[j][2]=0.f; s[j][3]=0.f; }
        #pragma unroll
        for (int ka = 0; ka < 2; ka++) {
            #pragma unroll
            for (int j = 0; j < 8; j++) {
                int r = (8 * j + g) * 20 + 8 * ka + tig;
                uint32_t bh[2] = { Kh[r], Kh[r + 4] };
                uint32_t bl[2] = { Kl[r], Kl[r + 4] };
                mma_bf16(s[j], qh[ka], bh);
                mma_bf16(s[j], qh[ka], bl);
                mma_bf16(s[j], ql[ka], bh);
            }
        }
        // mask tail keys
        if (k0 + 64 > 900) {
            #pragma unroll
            for (int j = 0; j < 8; j++) {
                int c = k0 + 8 * j + 2 * tig;
                if (c     >= 900) { s[j][0] = -1e30f; s[j][2] = -1e30f; }
                if (c + 1 >= 900) { s[j][1] = -1e30f; s[j][3] = -1e30f; }
            }
        }
        // ---- online softmax (rows g and g+8) ----
        float mx0 = -1e30f, mx1 = -1e30f;
        #pragma unroll
        for (int j = 0; j < 8; j++) {
            mx0 = fmaxf(mx0, fmaxf(s[j][0], s[j][1]));
            mx1 = fmaxf(mx1, fmaxf(s[j][2], s[j][3]));
        }
        mx0 = fmaxf(mx0, __shfl_xor_sync(0xFFFFFFFFu, mx0, 1));
        mx0 = fmaxf(mx0, __shfl_xor_sync(0xFFFFFFFFu, mx0, 2));
        mx1 = fmaxf(mx1, __shfl_xor_sync(0xFFFFFFFFu, mx1, 1));
        mx1 = fmaxf(mx1, __shfl_xor_sync(0xFFFFFFFFu, mx1, 2));
        float mn0 = fmaxf(m0, mx0), mn1 = fmaxf(m1, mx1);
        float c0 = __expf(m0 - mn0), c1 = __expf(m1 - mn1);
        m0 = mn0; m1 = mn1;
        #pragma unroll
        for (int n = 0; n < 4; n++) {
            out[n][0] *= c0; out[n][1] *= c0;
            out[n][2] *= c1; out[n][3] *= c1;
        }
        float sum0 = 0.f, sum1 = 0.f;
        uint32_t ph[4][4], pl[4][4];
        #pragma unroll
        for (int kp = 0; kp < 4; kp++) {
            int j0 = 2 * kp, j1 = 2 * kp + 1;
            float pa = __expf(s[j0][0] - mn0), pb = __expf(s[j0][1] - mn0);
            float pc = __expf(s[j0][2] - mn1), pd = __expf(s[j0][3] - mn1);
            float pe = __expf(s[j1][0] - mn0), pf = __expf(s[j1][1] - mn0);
            float pg = __expf(s[j1][2] - mn1), pq = __expf(s[j1][3] - mn1);
            sum0 += pa + pb + pe + pf;
            sum1 += pc + pd + pg + pq;
            split2(pa, pb, ph[kp][0], pl[kp][0]);
            split2(pc, pd, ph[kp][1], pl[kp][1]);
            split2(pe, pf, ph[kp][2], pl[kp][2]);
            split2(pg, pq, ph[kp][3], pl[kp][3]);
        }
        sum0 += __shfl_xor_sync(0xFFFFFFFFu, sum0, 1);
        sum0 += __shfl_xor_sync(0xFFFFFFFFu, sum0, 2);
        sum1 += __shfl_xor_sync(0xFFFFFFFFu, sum1, 1);
        sum1 += __shfl_xor_sync(0xFFFFFFFFu, sum1, 2);
        l0 = l0 * c0 + sum0;
        l1 = l1 * c1 + sum1;

        // ---- out += P.V ----
        #pragma unroll
        for (int kp = 0; kp < 4; kp++) {
            #pragma unroll
            for (int n = 0; n < 4; n++) {
                int r = (8 * n + g) * 36 + 8 * kp + tig;
                uint32_t bh[2] = { Vh[r], Vh[r + 4] };
                uint32_t bl[2] = { Vl[r], Vl[r + 4] };
                mma_bf16(out[n], ph[kp], bh);
                mma_bf16(out[n], ph[kp], bl);
                mma_bf16(out[n], pl[kp], bh);
            }
        }
    }

    // epilogue
    float i0 = 1.f / l0, i1 = 1.f / l1;
    int qg0 = q0 + wq + g, qg1 = qg0 + 8;
    #pragma unroll
    for (int n = 0; n < 4; n++) {
        int col = h * 32 + 8 * n + 2 * tig;
        if (qg0 < 900)
            *(float2*)(outp + (size_t)(b * 900 + qg0) * 256 + col)
                = make_float2(out[n][0] * i0, out[n][1] * i0);
        if (qg1 < 900)
            *(float2*)(outp + (size_t)(b * 900 + qg1) * 256 + col)
                = make_float2(out[n][2] * i1, out[n][3] * i1);
    }
}

// ---------------- MS-deformable sampling ---------------------------------------
__global__ __launch_bounds__(256)
void sample_kernel(const float* __restrict__ value, const float* __restrict__ off,
                   const float* __restrict__ aw, const float* __restrict__ ref,
                   float* __restrict__ outp)
{
    int bq = blockIdx.x;
    int b = bq / 900;
    int h = threadIdx.x >> 5, lane = threadIdx.x & 31;

    const int hs_arr[4] = {128, 64, 32, 16};
    const int ws_arr[4] = {128, 64, 32, 16};
    const int st_arr[4] = {0, 16384, 20480, 21504};

    const float* offp = off + (size_t)bq * 256 + h * 32;
    const float* ap   = aw  + (size_t)bq * 128 + h * 16;
    const float* refp = ref + (size_t)bq * 8;

    float acc = 0.f;
    #pragma unroll
    for (int l = 0; l < 4; l++) {
        int   hs  = hs_arr[l], ws = ws_arr[l];
        float hsf = (float)hs, wsf = (float)ws;
        const float* vbase = value + ((size_t)b * LEN_ + st_arr[l]) * 256 + h * 32 + lane;
        float rx = refp[l * 2], ry = refp[l * 2 + 1];
        #pragma unroll
        for (int p = 0; p < 4; p++) {
            float ox = offp[l * 8 + p * 2];
            float oy = offp[l * 8 + p * 2 + 1];
            float x = (rx + ox / wsf) * wsf - 0.5f;
            float y = (ry + oy / hsf) * hsf - 0.5f;
            float x0f = floorf(x), y0f = floorf(y);
            int   x0 = (int)x0f, y0 = (int)y0f;
            float wx = x - x0f, wy = y - y0f;
            float a = ap[l * 4 + p];
            float s = 0.f;
            #pragma unroll
            for (int cy = 0; cy < 2; cy++) {
                #pragma unroll
                for (int cx = 0; cx < 2; cx++) {
                    int xi = x0 + cx, yi = y0 + cy;
                    float wgt = (cx ? wx : 1.f - wx) * (cy ? wy : 1.f - wy);
                    if (xi >= 0 && xi < ws && yi >= 0 && yi < hs)
                        s += wgt * vbase[(size_t)(yi * ws + xi) * 256];
                }
            }
            acc += a * s;
        }
    }
    outp[(size_t)bq * 256 + h * 32 + lane] = acc;
}

// ---------------- launch --------------------------------------------------------
// word offsets into g_wh/g_wl for each weight matrix
#define WO_SA_IN   0
#define WO_SA_INV  65536     // rows 512..767 of sa_in
#define WO_SA_OUT  98304
#define WO_CA_OFF  131072
#define WO_CA_AW   163840
#define WO_CA_VAL  180224
#define WO_CA_OUT  212992
#define WO_F1      245760
#define WO_F2      376832

static inline void tgemm(const float* X, const uint32_t* Wh, const uint32_t* Wl,
                         const float* b, float* Y,
                         int M, int Nn, int K, int relu, const unsigned char* mask)
{
    dim3 g(Nn / 128, (M + 127) / 128);
    mma_gemm_kernel<<<g, 256>>>(X, Wh, Wl, b, Y, M, Nn, K, relu, mask);
}

extern "C" void kernel_launch(void* const* d_in, const int* in_sizes, int n_in,
                              void* d_out, int out_size)
{
    const float* tgt      = (const float*)d_in[0];
    const float* qpos     = (const float*)d_in[1];
    const float* refp     = (const float*)d_in[2];
    const float* src      = (const float*)d_in[3];
    const unsigned char* mask = (const unsigned char*)d_in[6];
    const float* sa_in_w  = (const float*)d_in[7];
    const float* sa_in_b  = (const float*)d_in[8];
    const float* sa_out_w = (const float*)d_in[9];
    const float* sa_out_b = (const float*)d_in[10];
    const float* ca_off_w = (const float*)d_in[11];
    const float* ca_off_b = (const float*)d_in[12];
    const float* ca_aw_w  = (const float*)d_in[13];
    const float* ca_aw_b  = (const float*)d_in[14];
    const float* ca_val_w = (const float*)d_in[15];
    const float* ca_val_b = (const float*)d_in[16];
    const float* ca_out_w = (const float*)d_in[17];
    const float* ca_out_b = (const float*)d_in[18];
    const float* n1_g = (const float*)d_in[19];
    const float* n1_b = (const float*)d_in[20];
    const float* n2_g = (const float*)d_in[21];
    const float* n2_b = (const float*)d_in[22];
    const float* n3_g = (const float*)d_in[23];
    const float* n3_b = (const float*)d_in[24];
    const float* f1_w = (const float*)d_in[25];
    const float* f1_b = (const float*)d_in[26];
    const float* f2_w = (const float*)d_in[27];
    const float* f2_b = (const float*)d_in[28];
    float* outp = (float*)d_out;

    float *p_qadd, *p_qk, *p_vp, *p_attn, *p_tmp, *p_tgt1, *p_q2;
    float *p_off, *p_aw, *p_value, *p_samp, *p_tgt2, *p_ffn1;
    uint32_t *p_wh, *p_wl;
    cudaGetSymbolAddress((void**)&p_qadd,  g_qadd);
    cudaGetSymbolAddress((void**)&p_qk,    g_qk);
    cudaGetSymbolAddress((void**)&p_vp,    g_vp);
    cudaGetSymbolAddress((void**)&p_attn,  g_attn);
    cudaGetSymbolAddress((void**)&p_tmp,   g_tmp);
    cudaGetSymbolAddress((void**)&p_tgt1,  g_tgt1);
    cudaGetSymbolAddress((void**)&p_q2,    g_q2);
    cudaGetSymbolAddress((void**)&p_off,   g_off);
    cudaGetSymbolAddress((void**)&p_aw,    g_aw);
    cudaGetSymbolAddress((void**)&p_value, g_value);
    cudaGetSymbolAddress((void**)&p_samp,  g_samp);
    cudaGetSymbolAddress((void**)&p_tgt2,  g_tgt2);
    cudaGetSymbolAddress((void**)&p_ffn1,  g_ffn1);
    cudaGetSymbolAddress((void**)&p_wh,    g_wh);
    cudaGetSymbolAddress((void**)&p_wl,    g_wl);

    const int nQ = RQ * CD;

    // 0) pre-split all weights to bf16 hi/lo
    struct { const float* w; int off; int words; } wt[8] = {
        { sa_in_w,  WO_SA_IN,  98304  },
        { sa_out_w, WO_SA_OUT, 32768  },
        { ca_off_w, WO_CA_OFF, 32768  },
        { ca_aw_w,  WO_CA_AW,  16384  },
        { ca_val_w, WO_CA_VAL, 32768  },
        { ca_out_w, WO_CA_OUT, 32768  },
        { f1_w,     WO_F1,     131072 },
        { f2_w,     WO_F2,     131072 },
    };
    for (int i = 0; i < 8; i++)
        split_w_kernel<<<(wt[i].words + 255) / 256, 256>>>(wt[i].w, p_wh + wt[i].off,
                                                           p_wl + wt[i].off, wt[i].words);

    // 1) q = tgt + query_pos
    add_kernel<<<(nQ + 255) / 256, 256>>>(tgt, qpos, p_qadd, nQ);
    // 2) QK projection
    tgemm(p_qadd, p_wh + WO_SA_IN, p_wl + WO_SA_IN, sa_in_b, p_qk, RQ, 512, 256, 0, nullptr);
    // 3) V projection
    tgemm(tgt, p_wh + WO_SA_INV, p_wl + WO_SA_INV, sa_in_b + 512, p_vp, RQ, 256, 256, 0, nullptr);
    // 4) tensor-core flash self-attention
    dim3 gatt(15, NHH, NB);
    fattn_mma_kernel<<<gatt, 128>>>(p_qk, p_vp, p_attn);
    // 5) out projection
    tgemm(p_attn, p_wh + WO_SA_OUT, p_wl + WO_SA_OUT, sa_out_b, p_tmp, RQ, 256, 256, 0, nullptr);
    // 6) tgt1 = LN(tgt + tgt2, n2)
    add_ln_kernel<<<RQ, 256>>>(tgt, p_tmp, n2_g, n2_b, p_tgt1);
    // 7) deformable query
    add_kernel<<<(nQ + 255) / 256, 256>>>(p_tgt1, qpos, p_q2, nQ);
    // 8) offsets
    tgemm(p_q2, p_wh + WO_CA_OFF, p_wl + WO_CA_OFF, ca_off_b, p_off, RQ, 256, 256, 0, nullptr);
    // 9) attention-weight logits
    tgemm(p_q2, p_wh + WO_CA_AW, p_wl + WO_CA_AW, ca_aw_b, p_aw, RQ, 128, 256, 0, nullptr);
    // 10) softmax over 16 sampling points
    softmax16_kernel<<<(RQ * 8 + 255) / 256, 256>>>(p_aw, RQ * 8);
    // 11) value projection (with padding mask)
    tgemm(src, p_wh + WO_CA_VAL, p_wl + WO_CA_VAL, ca_val_b, p_value, RV, 256, 256, 0, mask);
    // 12) bilinear sampling + weighted sum
    sample_kernel<<<RQ, 256>>>(p_value, p_off, p_aw, refp, p_samp);
    // 13) deformable out projection
    tgemm(p_samp, p_wh + WO_CA_OUT, p_wl + WO_CA_OUT, ca_out_b, p_tmp, RQ, 256, 256, 0, nullptr);
    // 14) tgt2 = LN(tgt1 + tmp, n1)
    add_ln_kernel<<<RQ, 256>>>(p_tgt1, p_tmp, n1_g, n1_b, p_tgt2);
    // 15) FFN up + relu
    tgemm(p_tgt2, p_wh + WO_F1, p_wl + WO_F1, f1_b, p_ffn1, RQ, 1024, 256, 1, nullptr);
    // 16) FFN down
    tgemm(p_ffn1, p_wh + WO_F2, p_wl + WO_F2, f2_b, p_tmp, RQ, 256, 1024, 0, nullptr);
    // 17) out = LN(tgt2 + tmp, n3)
    add_ln_kernel<<<RQ, 256>>>(p_tgt2, p_tmp, n3_g, n3_b, outp);
}

// round 5
// speedup vs baseline: 2.6154x; 1.1353x over previous
#include <cuda_runtime.h>
#include <cuda_bf16.h>
#include <math.h>
#include <stdint.h>

// Problem constants (static per reference)
#define NB    8
#define LQN   900
#define CD    256
#define NHH   8
#define DHH   32
#define DFFN_ 1024
#define LEN_  21760
#define RQ    (NB*LQN)    // 7200
#define RV    (NB*LEN_)   // 174080

// ---------------- scratch (device globals; no allocations allowed) -------------
__device__ float g_qk  [RQ*512];
__device__ float g_vp  [RQ*CD];
__device__ float g_attn[RQ*CD];
__device__ float g_tmp [RQ*CD];
__device__ float g_tgt1[RQ*CD];
__device__ float g_off [RQ*CD];
__device__ float g_aw  [RQ*128];
__device__ float g_value[(size_t)RV*CD];
__device__ float g_samp[RQ*CD];
__device__ float g_tgt2[RQ*CD];
__device__ float g_ffn1[RQ*DFFN_];
// pre-split weights (bf16x2 words)
__device__ uint32_t g_wh[507904];
__device__ uint32_t g_wl[507904];

// word offsets into g_wh/g_wl for each weight matrix
#define WO_SA_IN   0
#define WO_SA_INV  65536     // rows 512..767 of sa_in
#define WO_SA_OUT  98304
#define WO_CA_OFF  131072
#define WO_CA_AW   163840
#define WO_CA_VAL  180224
#define WO_CA_OUT  212992
#define WO_F1      245760
#define WO_F2      376832

// ================= bf16 split helpers ===========================================
__device__ __forceinline__ void split2(float x, float y, uint32_t& hi, uint32_t& lo)
{
    __nv_bfloat16 hx = __float2bfloat16(x);
    __nv_bfloat16 hy = __float2bfloat16(y);
    __nv_bfloat16 lx = __float2bfloat16(x - __bfloat162float(hx));
    __nv_bfloat16 ly = __float2bfloat16(y - __bfloat162float(hy));
    hi = (uint32_t)(*(unsigned short*)&hx) | ((uint32_t)(*(unsigned short*)&hy) << 16);
    lo = (uint32_t)(*(unsigned short*)&lx) | ((uint32_t)(*(unsigned short*)&ly) << 16);
}

__device__ __forceinline__ void mma_bf16(float* c, const uint32_t* a, const uint32_t* b)
{
    asm volatile(
        "mma.sync.aligned.m16n8k16.row.col.f32.bf16.bf16.f32 "
        "{%0,%1,%2,%3}, {%4,%5,%6,%7}, {%8,%9}, {%0,%1,%2,%3};"
        : "+f"(c[0]), "+f"(c[1]), "+f"(c[2]), "+f"(c[3])
        : "r"(a[0]), "r"(a[1]), "r"(a[2]), "r"(a[3]), "r"(b[0]), "r"(b[1]));
}

// ---------------- weight pre-split (single launch, 8 segments) ------------------
__global__ void split_all_kernel(const float* w0, const float* w1, const float* w2,
                                 const float* w3, const float* w4, const float* w5,
                                 const float* w6, const float* w7,
                                 uint32_t* __restrict__ Wh, uint32_t* __restrict__ Wl)
{
    const int offs [8] = { WO_SA_IN, WO_SA_OUT, WO_CA_OFF, WO_CA_AW,
                           WO_CA_VAL, WO_CA_OUT, WO_F1, WO_F2 };
    const int words[8] = { 98304, 32768, 32768, 16384, 32768, 32768, 131072, 131072 };
    int seg = blockIdx.y;
    int i = blockIdx.x * 256 + threadIdx.x;
    if (i >= words[seg]) return;
    const float* W;
    switch (seg) {
        case 0: W = w0; break; case 1: W = w1; break;
        case 2: W = w2; break; case 3: W = w3; break;
        case 4: W = w4; break; case 5: W = w5; break;
        case 6: W = w6; break; default: W = w7; break;
    }
    float2 v = *(const float2*)(W + 2 * (size_t)i);
    uint32_t h, l; split2(v.x, v.y, h, l);
    Wh[offs[seg] + i] = h;
    Wl[offs[seg] + i] = l;
}

// ================= pipelined tensor-core GEMM ====================================
// Y[M,N] = (X [+X2]) [M,K] @ W[N,K]^T + bias. bf16 hi/lo compensated (3 passes).
// Block tile 128x128, 256 threads = 8 warps (2m x 4n). Double-buffered SMEM with
// register prefetch of the next 32-K chunk.
#define GS 20            // words per SMEM row
#define BUFW (128*GS)    // words per array (2560)
#define GEMM_SMEM (2 * 4 * BUFW * 4)  // 81920 bytes

__global__ __launch_bounds__(256)
void mma_gemm_kernel(const float* __restrict__ X, const float* __restrict__ X2,
                     const uint32_t* __restrict__ Wh, const uint32_t* __restrict__ Wl,
                     const float* __restrict__ bias, float* __restrict__ Y,
                     int M, int Nn, int K, int relu, const unsigned char* __restrict__ mask)
{
    extern __shared__ uint32_t sm[];

    int tid = threadIdx.x, wid = tid >> 5, lane = tid & 31;
    int bm = blockIdx.y * 128, bn = blockIdx.x * 128;
    int wm = (wid >> 2) * 64;
    int wn = (wid & 3) * 32;
    int g = lane >> 2, tig = lane & 3;

    // per-thread staging coordinates (4 quads)
    int rowv[4], c4v[4], wrdv[4];
    #pragma unroll
    for (int i = 0; i < 4; i++) {
        int g4 = tid + i * 256;
        rowv[i] = g4 >> 3;
        c4v[i]  = (g4 & 7) * 4;
        wrdv[i] = rowv[i] * GS + (c4v[i] >> 1);
    }

    float acc[4][4][4];
    #pragma unroll
    for (int m = 0; m < 4; m++)
        #pragma unroll
        for (int n = 0; n < 4; n++)
            #pragma unroll
            for (int i = 0; i < 4; i++) acc[m][n][i] = 0.f;

    float4 av[4];
    uint2  bhv[4], blv[4];
    const int nch = K >> 5;

    // ---- prefetch helper (macro-style to keep regs) ----
    #define LOAD_CHUNK(kc_) do {                                                  \
        int kk_ = (kc_) * 32;                                                     \
        _Pragma("unroll")                                                         \
        for (int i = 0; i < 4; i++) {                                             \
            int gr = bm + rowv[i];                                                \
            if (gr < M) {                                                         \
                av[i] = *(const float4*)(X + (size_t)gr * K + kk_ + c4v[i]);      \
                if (X2) {                                                         \
                    float4 u = *(const float4*)(X2 + (size_t)gr * K + kk_ + c4v[i]); \
                    av[i].x += u.x; av[i].y += u.y; av[i].z += u.z; av[i].w += u.w;  \
                }                                                                 \
            } else av[i] = make_float4(0.f, 0.f, 0.f, 0.f);                       \
            size_t wo = ((size_t)(bn + rowv[i]) * K + kk_ + c4v[i]) >> 1;         \
            bhv[i] = *(const uint2*)(Wh + wo);                                    \
            blv[i] = *(const uint2*)(Wl + wo);                                    \
        }                                                                         \
    } while (0)

    #define STORE_CHUNK(buf_) do {                                                \
        uint32_t* base_ = sm + (buf_) * (4 * BUFW);                               \
        uint32_t* pAh = base_;                                                    \
        uint32_t* pAl = base_ + BUFW;                                             \
        uint32_t* pBh = base_ + 2 * BUFW;                                         \
        uint32_t* pBl = base_ + 3 * BUFW;                                         \
        _Pragma("unroll")                                                         \
        for (int i = 0; i < 4; i++) {                                             \
            uint32_t h0, l0, h1, l1;                                              \
            split2(av[i].x, av[i].y, h0, l0);                                     \
            split2(av[i].z, av[i].w, h1, l1);                                     \
            *(uint2*)(pAh + wrdv[i]) = make_uint2(h0, h1);                        \
            *(uint2*)(pAl + wrdv[i]) = make_uint2(l0, l1);                        \
            *(uint2*)(pBh + wrdv[i]) = bhv[i];                                    \
            *(uint2*)(pBl + wrdv[i]) = blv[i];                                    \
        }                                                                         \
    } while (0)

    LOAD_CHUNK(0);
    STORE_CHUNK(0);
    __syncthreads();

    for (int kc = 0; kc < nch; kc++) {
        int nb = kc + 1;
        if (nb < nch) LOAD_CHUNK(nb);

        uint32_t* base = sm + (kc & 1) * (4 * BUFW);
        uint32_t* sAh = base;
        uint32_t* sAl = base + BUFW;
        uint32_t* sBh = base + 2 * BUFW;
        uint32_t* sBl = base + 3 * BUFW;

        #pragma unroll
        for (int ka = 0; ka < 2; ka++) {
            int kw = ka * 8 + tig;
            uint32_t ah[4][4], al[4][4];
            #pragma unroll
            for (int m = 0; m < 4; m++) {
                int r = wm + m * 16 + g;
                ah[m][0] = sAh[r * GS + kw];
                ah[m][1] = sAh[(r + 8) * GS + kw];
                ah[m][2] = sAh[r * GS + kw + 4];
                ah[m][3] = sAh[(r + 8) * GS + kw + 4];
                al[m][0] = sAl[r * GS + kw];
                al[m][1] = sAl[(r + 8) * GS + kw];
                al[m][2] = sAl[r * GS + kw + 4];
                al[m][3] = sAl[(r + 8) * GS + kw + 4];
            }
            uint32_t bh[4][2], bl[4][2];
            #pragma unroll
            for (int n = 0; n < 4; n++) {
                int rn = wn + n * 8 + g;
                bh[n][0] = sBh[rn * GS + kw];
                bh[n][1] = sBh[rn * GS + kw + 4];
                bl[n][0] = sBl[rn * GS + kw];
                bl[n][1] = sBl[rn * GS + kw + 4];
            }
            #pragma unroll
            for (int m = 0; m < 4; m++)
                #pragma unroll
                for (int n = 0; n < 4; n++) {
                    mma_bf16(acc[m][n], ah[m], bh[n]);
                    mma_bf16(acc[m][n], ah[m], bl[n]);
                    mma_bf16(acc[m][n], al[m], bh[n]);
                }
        }
        if (nb < nch) STORE_CHUNK(nb & 1);
        __syncthreads();
    }

    // -------- epilogue ---------------------------------------------------------
    #pragma unroll
    for (int m = 0; m < 4; m++) {
        int r0 = bm + wm + m * 16 + g;
        #pragma unroll
        for (int n = 0; n < 4; n++) {
            int c0 = bn + wn + n * 8 + 2 * tig;
            float b0 = bias[c0], b1 = bias[c0 + 1];
            if (r0 < M) {
                float v0 = acc[m][n][0] + b0;
                float v1 = acc[m][n][1] + b1;
                if (relu) { v0 = fmaxf(v0, 0.f); v1 = fmaxf(v1, 0.f); }
                if (mask && mask[r0]) { v0 = 0.f; v1 = 0.f; }
                *(float2*)(Y + (size_t)r0 * Nn + c0) = make_float2(v0, v1);
            }
            if (r0 + 8 < M) {
                float v2 = acc[m][n][2] + b0;
                float v3 = acc[m][n][3] + b1;
                if (relu) { v2 = fmaxf(v2, 0.f); v3 = fmaxf(v3, 0.f); }
                if (mask && mask[r0 + 8]) { v2 = 0.f; v3 = 0.f; }
                *(float2*)(Y + (size_t)(r0 + 8) * Nn + c0) = make_float2(v2, v3);
            }
        }
    }
}

// ---------------- Y = LayerNorm(A+B) over C=256, per-row block -----------------
__global__ __launch_bounds__(256)
void add_ln_kernel(const float* __restrict__ A, const float* __restrict__ B,
                   const float* __restrict__ g, const float* __restrict__ bt,
                   float* __restrict__ Y)
{
    int r = blockIdx.x;
    int c = threadIdx.x;
    size_t idx = (size_t)r * 256 + c;
    float x = A[idx] + B[idx];
    __shared__ float s1[8], s2[8];
    float v1 = x, v2 = x * x;
    #pragma unroll
    for (int o = 16; o > 0; o >>= 1) {
        v1 += __shfl_xor_sync(0xFFFFFFFFu, v1, o);
        v2 += __shfl_xor_sync(0xFFFFFFFFu, v2, o);
    }
    int w = c >> 5;
    if ((c & 31) == 0) { s1[w] = v1; s2[w] = v2; }
    __syncthreads();
    float t1 = 0.f, t2 = 0.f;
    #pragma unroll
    for (int i = 0; i < 8; i++) { t1 += s1[i]; t2 += s2[i]; }
    float mean = t1 * (1.f/256.f);
    float var  = t2 * (1.f/256.f) - mean * mean;
    float inv  = rsqrtf(var + 1e-5f);
    Y[idx] = (x - mean) * inv * g[c] + bt[c];
}

// ---------------- softmax over groups of 16 (attention weights) ----------------
__global__ void softmax16_kernel(float* __restrict__ a, int rows)
{
    int r = blockIdx.x * blockDim.x + threadIdx.x;
    if (r >= rows) return;
    float* p = a + (size_t)r * 16;
    float e[16];
    float m = p[0];
    #pragma unroll
    for (int i = 1; i < 16; i++) m = fmaxf(m, p[i]);
    float s = 0.f;
    #pragma unroll
    for (int i = 0; i < 16; i++) { e[i] = expf(p[i] - m); s += e[i]; }
    float inv = 1.f / s;
    #pragma unroll
    for (int i = 0; i < 16; i++) p[i] = e[i] * inv;
}

// ---------------- tensor-core flash self-attention ------------------------------
// grid (15, NH, NB), 128 threads = 4 warps, 16 queries/warp, 64-key tiles.
__global__ __launch_bounds__(128)
void fattn_mma_kernel(const float* __restrict__ qk, const float* __restrict__ vp,
                      float* __restrict__ outp)
{
    __shared__ uint32_t Qh[64*20], Ql[64*20];
    __shared__ uint32_t Kh[64*20], Kl[64*20];
    __shared__ uint32_t Vh[32*36], Vl[32*36];

    int b = blockIdx.z, h = blockIdx.y, qb = blockIdx.x;
    int tid = threadIdx.x, w = tid >> 5, lane = tid & 31;
    int g = lane >> 2, tig = lane & 3;
    int q0 = qb * 64;
    const float scale = 0.17677669529663687f;   // 1/sqrt(32)

    for (int idx = tid; idx < 64 * 16; idx += 128) {
        int row = idx >> 4, wc = idx & 15;
        int qg = q0 + row;
        float2 v = make_float2(0.f, 0.f);
        if (qg < 900) v = *(const float2*)(qk + (size_t)(b * 900 + qg) * 512 + h * 32 + 2 * wc);
        uint32_t hi, lo; split2(v.x * scale, v.y * scale, hi, lo);
        Qh[row * 20 + wc] = hi; Ql[row * 20 + wc] = lo;
    }
    __syncthreads();

    uint32_t qh[2][4], ql[2][4];
    int wq = w * 16;
    #pragma unroll
    for (int ka = 0; ka < 2; ka++) {
        int base = 8 * ka + tig;
        qh[ka][0] = Qh[(wq + g) * 20 + base];     qh[ka][1] = Qh[(wq + g + 8) * 20 + base];
        qh[ka][2] = Qh[(wq + g) * 20 + base + 4]; qh[ka][3] = Qh[(wq + g + 8) * 20 + base + 4];
        ql[ka][0] = Ql[(wq + g) * 20 + base];     ql[ka][1] = Ql[(wq + g + 8) * 20 + base];
        ql[ka][2] = Ql[(wq + g) * 20 + base + 4]; ql[ka][3] = Ql[(wq + g + 8) * 20 + base + 4];
    }

    float out[4][4];
    #pragma unroll
    for (int n = 0; n < 4; n++) { out[n][0]=0.f; out[n][1]=0.f; out[n][2]=0.f; out[n][3]=0.f; }
    float m0 = -1e30f, m1 = -1e30f, l0 = 0.f, l1 = 0.f;

    for (int kt = 0; kt < 15; kt++) {
        int k0 = kt * 64;
        __syncthreads();
        for (int idx = tid; idx < 64 * 16; idx += 128) {
            int row = idx >> 4, wc = idx & 15;
            int kg = k0 + row;
            float2 v = make_float2(0.f, 0.f);
            if (kg < 900)
                v = *(const float2*)(qk + (size_t)(b * 900 + kg) * 512 + 256 + h * 32 + 2 * wc);
            uint32_t hi, lo; split2(v.x, v.y, hi, lo);
            Kh[row * 20 + wc] = hi; Kl[row * 20 + wc] = lo;
        }
        for (int idx = tid; idx < 32 * 32; idx += 128) {
            int d = idx >> 5, wc = idx & 31;
            int kg = k0 + 2 * wc;
            float v0 = (kg     < 900) ? vp[(size_t)(b * 900 + kg    ) * 256 + h * 32 + d] : 0.f;
            float v1 = (kg + 1 < 900) ? vp[(size_t)(b * 900 + kg + 1) * 256 + h * 32 + d] : 0.f;
            uint32_t hi, lo; split2(v0, v1, hi, lo);
            Vh[d * 36 + wc] = hi; Vl[d * 36 + wc] = lo;
        }
        __syncthreads();

        float s[8][4];
        #pragma unroll
        for (int j = 0; j < 8; j++) { s[j][0]=0.f; s[j][1]=0.f; s[j][2]=0.f; s[j][3]=0.f; }
        #pragma unroll
        for (int ka = 0; ka < 2; ka++) {
            #pragma unroll
            for (int j = 0; j < 8; j++) {
                int r = (8 * j + g) * 20 + 8 * ka + tig;
                uint32_t bh[2] = { Kh[r], Kh[r + 4] };
                uint32_t bl[2] = { Kl[r], Kl[r + 4] };
                mma_bf16(s[j], qh[ka], bh);
                mma_bf16(s[j], qh[ka], bl);
                mma_bf16(s[j], ql[ka], bh);
            }
        }
        if (k0 + 64 > 900) {
            #pragma unroll
            for (int j = 0; j < 8; j++) {
                int c = k0 + 8 * j + 2 * tig;
                if (c     >= 900) { s[j][0] = -1e30f; s[j][2] = -1e30f; }
                if (c + 1 >= 900) { s[j][1] = -1e30f; s[j][3] = -1e30f; }
            }
        }
        float mx0 = -1e30f, mx1 = -1e30f;
        #pragma unroll
        for (int j = 0; j < 8; j++) {
            mx0 = fmaxf(mx0, fmaxf(s[j][0], s[j][1]));
            mx1 = fmaxf(mx1, fmaxf(s[j][2], s[j][3]));
        }
        mx0 = fmaxf(mx0, __shfl_xor_sync(0xFFFFFFFFu, mx0, 1));
        mx0 = fmaxf(mx0, __shfl_xor_sync(0xFFFFFFFFu, mx0, 2));
        mx1 = fmaxf(mx1, __shfl_xor_sync(0xFFFFFFFFu, mx1, 1));
        mx1 = fmaxf(mx1, __shfl_xor_sync(0xFFFFFFFFu, mx1, 2));
        float mn0 = fmaxf(m0, mx0), mn1 = fmaxf(m1, mx1);
        float c0 = __expf(m0 - mn0), c1 = __expf(m1 - mn1);
        m0 = mn0; m1 = mn1;
        #pragma unroll
        for (int n = 0; n < 4; n++) {
            out[n][0] *= c0; out[n][1] *= c0;
            out[n][2] *= c1; out[n][3] *= c1;
        }
        float sum0 = 0.f, sum1 = 0.f;
        uint32_t ph[4][4], pl[4][4];
        #pragma unroll
        for (int kp = 0; kp < 4; kp++) {
            int j0 = 2 * kp, j1 = 2 * kp + 1;
            float pa = __expf(s[j0][0] - mn0), pb = __expf(s[j0][1] - mn0);
            float pc = __expf(s[j0][2] - mn1), pd = __expf(s[j0][3] - mn1);
            float pe = __expf(s[j1][0] - mn0), pf = __expf(s[j1][1] - mn0);
            float pg = __expf(s[j1][2] - mn1), pq = __expf(s[j1][3] - mn1);
            sum0 += pa + pb + pe + pf;
            sum1 += pc + pd + pg + pq;
            split2(pa, pb, ph[kp][0], pl[kp][0]);
            split2(pc, pd, ph[kp][1], pl[kp][1]);
            split2(pe, pf, ph[kp][2], pl[kp][2]);
            split2(pg, pq, ph[kp][3], pl[kp][3]);
        }
        sum0 += __shfl_xor_sync(0xFFFFFFFFu, sum0, 1);
        sum0 += __shfl_xor_sync(0xFFFFFFFFu, sum0, 2);
        sum1 += __shfl_xor_sync(0xFFFFFFFFu, sum1, 1);
        sum1 += __shfl_xor_sync(0xFFFFFFFFu, sum1, 2);
        l0 = l0 * c0 + sum0;
        l1 = l1 * c1 + sum1;

        #pragma unroll
        for (int kp = 0; kp < 4; kp++) {
            #pragma unroll
            for (int n = 0; n < 4; n++) {
                int r = (8 * n + g) * 36 + 8 * kp + tig;
                uint32_t bh[2] = { Vh[r], Vh[r + 4] };
                uint32_t bl[2] = { Vl[r], Vl[r + 4] };
                mma_bf16(out[n], ph[kp], bh);
                mma_bf16(out[n], ph[kp], bl);
                mma_bf16(out[n], pl[kp], bh);
            }
        }
    }

    float i0 = 1.f / l0, i1 = 1.f / l1;
    int qg0 = q0 + wq + g, qg1 = qg0 + 8;
    #pragma unroll
    for (int n = 0; n < 4; n++) {
        int col = h * 32 + 8 * n + 2 * tig;
        if (qg0 < 900)
            *(float2*)(outp + (size_t)(b * 900 + qg0) * 256 + col)
                = make_float2(out[n][0] * i0, out[n][1] * i0);
        if (qg1 < 900)
            *(float2*)(outp + (size_t)(b * 900 + qg1) * 256 + col)
                = make_float2(out[n][2] * i1, out[n][3] * i1);
    }
}

// ---------------- MS-deformable sampling ---------------------------------------
__global__ __launch_bounds__(256)
void sample_kernel(const float* __restrict__ value, const float* __restrict__ off,
                   const float* __restrict__ aw, const float* __restrict__ ref,
                   float* __restrict__ outp)
{
    int bq = blockIdx.x;
    int b = bq / 900;
    int h = threadIdx.x >> 5, lane = threadIdx.x & 31;

    const int hs_arr[4] = {128, 64, 32, 16};
    const int ws_arr[4] = {128, 64, 32, 16};
    const int st_arr[4] = {0, 16384, 20480, 21504};

    const float* offp = off + (size_t)bq * 256 + h * 32;
    const float* ap   = aw  + (size_t)bq * 128 + h * 16;
    const float* refp = ref + (size_t)bq * 8;

    float acc = 0.f;
    #pragma unroll
    for (int l = 0; l < 4; l++) {
        int   hs  = hs_arr[l], ws = ws_arr[l];
        float hsf = (float)hs, wsf = (float)ws;
        const float* vbase = value + ((size_t)b * LEN_ + st_arr[l]) * 256 + h * 32 + lane;
        float rx = refp[l * 2], ry = refp[l * 2 + 1];
        #pragma unroll
        for (int p = 0; p < 4; p++) {
            float ox = offp[l * 8 + p * 2];
            float oy = offp[l * 8 + p * 2 + 1];
            float x = (rx + ox / wsf) * wsf - 0.5f;
            float y = (ry + oy / hsf) * hsf - 0.5f;
            float x0f = floorf(x), y0f = floorf(y);
            int   x0 = (int)x0f, y0 = (int)y0f;
            float wx = x - x0f, wy = y - y0f;
            float a = ap[l * 4 + p];
            float s = 0.f;
            #pragma unroll
            for (int cy = 0; cy < 2; cy++) {
                #pragma unroll
                for (int cx = 0; cx < 2; cx++) {
                    int xi = x0 + cx, yi = y0 + cy;
                    float wgt = (cx ? wx : 1.f - wx) * (cy ? wy : 1.f - wy);
                    if (xi >= 0 && xi < ws && yi >= 0 && yi < hs)
                        s += wgt * vbase[(size_t)(yi * ws + xi) * 256];
                }
            }
            acc += a * s;
        }
    }
    outp[(size_t)bq * 256 + h * 32 + lane] = acc;
}

// ---------------- launch --------------------------------------------------------
static inline void tgemm(const float* X, const float* X2,
                         const uint32_t* Wh, const uint32_t* Wl,
                         const float* b, float* Y,
                         int M, int Nn, int K, int relu, const unsigned char* mask)
{
    dim3 g(Nn / 128, (M + 127) / 128);
    mma_gemm_kernel<<<g, 256, GEMM_SMEM>>>(X, X2, Wh, Wl, b, Y, M, Nn, K, relu, mask);
}

extern "C" void kernel_launch(void* const* d_in, const int* in_sizes, int n_in,
                              void* d_out, int out_size)
{
    const float* tgt      = (const float*)d_in[0];
    const float* qpos     = (const float*)d_in[1];
    const float* refp     = (const float*)d_in[2];
    const float* src      = (const float*)d_in[3];
    const unsigned char* mask = (const unsigned char*)d_in[6];
    const float* sa_in_w  = (const float*)d_in[7];
    const float* sa_in_b  = (const float*)d_in[8];
    const float* sa_out_w = (const float*)d_in[9];
    const float* sa_out_b = (const float*)d_in[10];
    const float* ca_off_w = (const float*)d_in[11];
    const float* ca_off_b = (const float*)d_in[12];
    const float* ca_aw_w  = (const float*)d_in[13];
    const float* ca_aw_b  = (const float*)d_in[14];
    const float* ca_val_w = (const float*)d_in[15];
    const float* ca_val_b = (const float*)d_in[16];
    const float* ca_out_w = (const float*)d_in[17];
    const float* ca_out_b = (const float*)d_in[18];
    const float* n1_g = (const float*)d_in[19];
    const float* n1_b = (const float*)d_in[20];
    const float* n2_g = (const float*)d_in[21];
    const float* n2_b = (const float*)d_in[22];
    const float* n3_g = (const float*)d_in[23];
    const float* n3_b = (const float*)d_in[24];
    const float* f1_w = (const float*)d_in[25];
    const float* f1_b = (const float*)d_in[26];
    const float* f2_w = (const float*)d_in[27];
    const float* f2_b = (const float*)d_in[28];
    float* outp = (float*)d_out;

    float *p_qk, *p_vp, *p_attn, *p_tmp, *p_tgt1;
    float *p_off, *p_aw, *p_value, *p_samp, *p_tgt2, *p_ffn1;
    uint32_t *p_wh, *p_wl;
    cudaGetSymbolAddress((void**)&p_qk,    g_qk);
    cudaGetSymbolAddress((void**)&p_vp,    g_vp);
    cudaGetSymbolAddress((void**)&p_attn,  g_attn);
    cudaGetSymbolAddress((void**)&p_tmp,   g_tmp);
    cudaGetSymbolAddress((void**)&p_tgt1,  g_tgt1);
    cudaGetSymbolAddress((void**)&p_off,   g_off);
    cudaGetSymbolAddress((void**)&p_aw,    g_aw);
    cudaGetSymbolAddress((void**)&p_value, g_value);
    cudaGetSymbolAddress((void**)&p_samp,  g_samp);
    cudaGetSymbolAddress((void**)&p_tgt2,  g_tgt2);
    cudaGetSymbolAddress((void**)&p_ffn1,  g_ffn1);
    cudaGetSymbolAddress((void**)&p_wh,    g_wh);
    cudaGetSymbolAddress((void**)&p_wl,    g_wl);

    cudaFuncSetAttribute(mma_gemm_kernel, cudaFuncAttributeMaxDynamicSharedMemorySize,
                         GEMM_SMEM);

    // 0) pre-split all weights (one launch)
    dim3 gsplit(512, 8);
    split_all_kernel<<<gsplit, 256>>>(sa_in_w, sa_out_w, ca_off_w, ca_aw_w,
                                      ca_val_w, ca_out_w, f1_w, f2_w, p_wh, p_wl);

    // 1) QK projection, A = tgt + qpos (fused)
    tgemm(tgt, qpos, p_wh + WO_SA_IN, p_wl + WO_SA_IN, sa_in_b, p_qk, RQ, 512, 256, 0, nullptr);
    // 2) V projection
    tgemm(tgt, nullptr, p_wh + WO_SA_INV, p_wl + WO_SA_INV, sa_in_b + 512, p_vp,
          RQ, 256, 256, 0, nullptr);
    // 3) tensor-core flash self-attention
    dim3 gatt(15, NHH, NB);
    fattn_mma_kernel<<<gatt, 128>>>(p_qk, p_vp, p_attn);
    // 4) out projection
    tgemm(p_attn, nullptr, p_wh + WO_SA_OUT, p_wl + WO_SA_OUT, sa_out_b, p_tmp,
          RQ, 256, 256, 0, nullptr);
    // 5) tgt1 = LN(tgt + tmp, n2)
    add_ln_kernel<<<RQ, 256>>>(tgt, p_tmp, n2_g, n2_b, p_tgt1);
    // 6) offsets, A = tgt1 + qpos (fused)
    tgemm(p_tgt1, qpos, p_wh + WO_CA_OFF, p_wl + WO_CA_OFF, ca_off_b, p_off,
          RQ, 256, 256, 0, nullptr);
    // 7) attention-weight logits, A = tgt1 + qpos (fused)
    tgemm(p_tgt1, qpos, p_wh + WO_CA_AW, p_wl + WO_CA_AW, ca_aw_b, p_aw,
          RQ, 128, 256, 0, nullptr);
    // 8) softmax over 16 sampling points
    softmax16_kernel<<<(RQ * 8 + 255) / 256, 256>>>(p_aw, RQ * 8);
    // 9) value projection (with padding mask)
    tgemm(src, nullptr, p_wh + WO_CA_VAL, p_wl + WO_CA_VAL, ca_val_b, p_value,
          RV, 256, 256, 0, mask);
    // 10) bilinear sampling + weighted sum
    sample_kernel<<<RQ, 256>>>(p_value, p_off, p_aw, refp, p_samp);
    // 11) deformable out projection
    tgemm(p_samp, nullptr, p_wh + WO_CA_OUT, p_wl + WO_CA_OUT, ca_out_b, p_tmp,
          RQ, 256, 256, 0, nullptr);
    // 12) tgt2 = LN(tgt1 + tmp, n1)
    add_ln_kernel<<<RQ, 256>>>(p_tgt1, p_tmp, n1_g, n1_b, p_tgt2);
    // 13) FFN up + relu
    tgemm(p_tgt2, nullptr, p_wh + WO_F1, p_wl + WO_F1, f1_b, p_ffn1,
          RQ, 1024, 256, 1, nullptr);
    // 14) FFN down
    tgemm(p_ffn1, nullptr, p_wh + WO_F2, p_wl + WO_F2, f2_b, p_tmp,
          RQ, 256, 1024, 0, nullptr);
    // 15) out = LN(tgt2 + tmp, n3)
    add_ln_kernel<<<RQ, 256>>>(p_tgt2, p_tmp, n3_g, n3_b, outp);
}